// round 13
// baseline (speedup 1.0000x reference)
#include <cuda_runtime.h>
#include <cuda_bf16.h>
#include <math.h>
#include <stdint.h>

#define BB   16384
#define DIM  1024
#define HID  64

typedef uint32_t u32;

// ---------------- device scratch (no allocations allowed) ----------------
__device__ float g_w2s[HID];
__device__ float g_invm[DIM];
__device__ float g_Gq[HID*HID];   // W1q^T W1p
__device__ float g_Gm[HID*HID];   // W1q^T diag(1/m) W1q
__device__ float g_part[32*4096]; // Gram partials (variant,kc)

// bf16 hi/lo pre-split weights
__device__ __align__(16) __nv_bfloat16 g_W1qT_h[HID*DIM],  g_W1qT_l[HID*DIM];   // [j][k]
__device__ __align__(16) __nv_bfloat16 g_W1pT_h[HID*DIM],  g_W1pT_l[HID*DIM];   // [j][k]
__device__ __align__(16) __nv_bfloat16 g_W1qmT_h[HID*DIM], g_W1qmT_l[HID*DIM];  // [j][k] invm folded
__device__ __align__(16) __nv_bfloat16 g_W1qB_h[DIM*HID],  g_W1qB_l[DIM*HID];   // [d][j]
__device__ __align__(16) __nv_bfloat16 g_W2TB_h[DIM*HID],  g_W2TB_l[DIM*HID];   // [d][j] = W2[j][d]
__device__ __align__(16) __nv_bfloat16 g_G1T_h[HID*HID],   g_G1T_l[HID*HID];    // [j2][j1] hdt*Gq+dt*hdt*Gm
__device__ __align__(16) __nv_bfloat16 g_GqT_h[HID*HID],   g_GqT_l[HID*HID];    // [j2][j1] hdt*Gq

// ---------------- scalar helpers ----------------
__device__ __forceinline__ float dt_of(const float* dtp){
    float x = __ldg(dtp);
    return 1.0f/(1.0f + expf(-x));
}
__device__ __forceinline__ float gelu_f(float x){
    return x * 0.5f * (1.0f + erff(x * 0.70710678118654752440f));
}
__device__ __forceinline__ float dgelu_f(float x){
    float cdf = 0.5f * (1.0f + erff(x * 0.70710678118654752440f));
    float pdf = 0.39894228040143267794f * expf(-0.5f * x * x);
    return cdf + x * pdf;
}

// ---------------- smem primitives ----------------
__device__ __forceinline__ u32 s2u(const void* p){
    u32 a;
    asm("{ .reg .u64 t; cvta.to.shared.u64 t, %1; cvt.u32.u64 %0, t; }" : "=r"(a) : "l"(p));
    return a;
}
__device__ __forceinline__ void sts16(u32 a, unsigned short v){ asm volatile("st.shared.b16 [%0], %1;" :: "r"(a), "h"(v)); }
__device__ __forceinline__ void sts32f(u32 a, float v){ asm volatile("st.shared.f32 [%0], %1;" :: "r"(a), "f"(v)); }
__device__ __forceinline__ void sts64(u32 a, u32 x, u32 y){ asm volatile("st.shared.v2.b32 [%0], {%1,%2};" :: "r"(a), "r"(x), "r"(y)); }
__device__ __forceinline__ void sts64f(u32 a, float x, float y){ asm volatile("st.shared.v2.f32 [%0], {%1,%2};" :: "r"(a), "f"(x), "f"(y)); }
__device__ __forceinline__ void sts128(u32 a, uint4 v){ asm volatile("st.shared.v4.b32 [%0], {%1,%2,%3,%4};" :: "r"(a), "r"(v.x), "r"(v.y), "r"(v.z), "r"(v.w)); }
__device__ __forceinline__ float ldsf(u32 a){ float v; asm volatile("ld.shared.f32 %0, [%1];" : "=f"(v) : "r"(a)); return v; }
__device__ __forceinline__ float4 lds128f(u32 a){ float4 v; asm volatile("ld.shared.v4.f32 {%0,%1,%2,%3}, [%4];" : "=f"(v.x),"=f"(v.y),"=f"(v.z),"=f"(v.w) : "r"(a)); return v; }

__device__ __forceinline__ u32 pack2(__nv_bfloat16 a, __nv_bfloat16 b){
    return (u32)__bfloat16_as_ushort(a) | ((u32)__bfloat16_as_ushort(b) << 16);
}

// ---------------- MMA primitives ----------------
// A-tile fragment (m16 x k16) from [row][k] layout, row stride 144 bytes
__device__ __forceinline__ void ldA(u32 base, int rowbase, int ks, int l, u32 a[4]){
    u32 addr = base + (u32)(rowbase + (l & 15))*144u + (u32)(((l >> 4)*8 + ks*16)*2);
    asm volatile("ldmatrix.sync.aligned.m8n8.x4.shared.b16 {%0,%1,%2,%3}, [%4];"
        : "=r"(a[0]), "=r"(a[1]), "=r"(a[2]), "=r"(a[3]) : "r"(addr));
}
// B-tile fragment (n8 x k16) from [n][k] layout, row stride 144 bytes
__device__ __forceinline__ void ldB(u32 base, int nrow, int ks, int l, u32 b[2]){
    u32 addr = base + (u32)(nrow + (l & 7))*144u + (u32)(((((l >> 3) & 1)*8) + ks*16)*2);
    asm volatile("ldmatrix.sync.aligned.m8n8.x2.shared.b16 {%0,%1}, [%2];"
        : "=r"(b[0]), "=r"(b[1]) : "r"(addr));
}
__device__ __forceinline__ void mm(float c[4], const u32 a[4], const u32 b[2]){
    asm volatile("mma.sync.aligned.m16n8k16.row.col.f32.bf16.bf16.f32 "
        "{%0,%1,%2,%3}, {%4,%5,%6,%7}, {%8,%9}, {%0,%1,%2,%3};"
        : "+f"(c[0]), "+f"(c[1]), "+f"(c[2]), "+f"(c[3])
        : "r"(a[0]), "r"(a[1]), "r"(a[2]), "r"(a[3]), "r"(b[0]), "r"(b[1]));
}

// K=64 3-term GEMM: acc[2][4][4] += A(64x64 hi/lo) x B(64x64 hi/lo)^T
// warp tile: 32 rows (mr) x 32 cols (nc)
__device__ __forceinline__ void gemmK64(float acc[2][4][4], u32 AH, u32 AL,
                                        u32 BH, u32 BL, int mr, int nc, int l){
    #pragma unroll
    for (int ks = 0; ks < 4; ++ks){
        u32 ah[2][4], al[2][4];
        ldA(AH, mr,     ks, l, ah[0]);
        ldA(AH, mr+16,  ks, l, ah[1]);
        ldA(AL, mr,     ks, l, al[0]);
        ldA(AL, mr+16,  ks, l, al[1]);
        #pragma unroll
        for (int nb = 0; nb < 4; ++nb){
            u32 bh[2], bl[2];
            ldB(BH, nc + nb*8, ks, l, bh);
            ldB(BL, nc + nb*8, ks, l, bl);
            #pragma unroll
            for (int i = 0; i < 2; ++i){
                mm(acc[i][nb], ah[i], bh);
                mm(acc[i][nb], ah[i], bl);
                mm(acc[i][nb], al[i], bh);
            }
        }
    }
}
// dual-B variant: accZ += A x B0, accV += A x B1 (shared A fragments)
__device__ __forceinline__ void gemmK64_dualB(float accZ[2][4][4], float accV[2][4][4],
                                              u32 AH, u32 AL,
                                              u32 B0H, u32 B0L, u32 B1H, u32 B1L,
                                              int mr, int nc, int l){
    #pragma unroll
    for (int ks = 0; ks < 4; ++ks){
        u32 ah[2][4], al[2][4];
        ldA(AH, mr,     ks, l, ah[0]);
        ldA(AH, mr+16,  ks, l, ah[1]);
        ldA(AL, mr,     ks, l, al[0]);
        ldA(AL, mr+16,  ks, l, al[1]);
        #pragma unroll
        for (int nb = 0; nb < 4; ++nb){
            u32 bh[2], bl[2], ch[2], cl[2];
            ldB(B0H, nc + nb*8, ks, l, bh);
            ldB(B0L, nc + nb*8, ks, l, bl);
            ldB(B1H, nc + nb*8, ks, l, ch);
            ldB(B1L, nc + nb*8, ks, l, cl);
            #pragma unroll
            for (int i = 0; i < 2; ++i){
                mm(accZ[i][nb], ah[i], bh);
                mm(accZ[i][nb], ah[i], bl);
                mm(accZ[i][nb], al[i], bh);
                mm(accV[i][nb], ah[i], ch);
                mm(accV[i][nb], ah[i], cl);
                mm(accV[i][nb], al[i], ch);
            }
        }
    }
}
// dual-A variant: accA += A1 x B, accC += A2 x B (shared B fragments)
__device__ __forceinline__ void gemmK64_dualA(float accA[2][4][4], float accC[2][4][4],
                                              u32 A1H, u32 A1L, u32 A2H, u32 A2L,
                                              u32 BH, u32 BL, int mr, int nc, int l){
    #pragma unroll
    for (int ks = 0; ks < 4; ++ks){
        u32 ah1[2][4], al1[2][4], ah2[2][4], al2[2][4];
        ldA(A1H, mr,     ks, l, ah1[0]);
        ldA(A1H, mr+16,  ks, l, ah1[1]);
        ldA(A1L, mr,     ks, l, al1[0]);
        ldA(A1L, mr+16,  ks, l, al1[1]);
        ldA(A2H, mr,     ks, l, ah2[0]);
        ldA(A2H, mr+16,  ks, l, ah2[1]);
        ldA(A2L, mr,     ks, l, al2[0]);
        ldA(A2L, mr+16,  ks, l, al2[1]);
        #pragma unroll
        for (int nb = 0; nb < 4; ++nb){
            u32 bh[2], bl[2];
            ldB(BH, nc + nb*8, ks, l, bh);
            ldB(BL, nc + nb*8, ks, l, bl);
            #pragma unroll
            for (int i = 0; i < 2; ++i){
                mm(accA[i][nb], ah1[i], bh);
                mm(accA[i][nb], ah1[i], bl);
                mm(accA[i][nb], al1[i], bh);
                mm(accC[i][nb], ah2[i], bh);
                mm(accC[i][nb], ah2[i], bl);
                mm(accC[i][nb], al2[i], bh);
            }
        }
    }
}

// convert 64x64 fp32 chunk (row stride DIM) -> hi/lo bf16 tiles [64][72]  (128 threads)
__device__ __forceinline__ void conv_tile(u32 dh, u32 dl, const float* __restrict__ src, int t){
    #pragma unroll
    for (int i = 0; i < 8; ++i){
        int e = t + i*128;
        int row = e >> 4, c4 = e & 15;
        float4 v = *(const float4*)(src + (size_t)row*DIM + c4*4);
        __nv_bfloat16 h0=__float2bfloat16_rn(v.x), h1=__float2bfloat16_rn(v.y),
                      h2=__float2bfloat16_rn(v.z), h3=__float2bfloat16_rn(v.w);
        float l0=v.x-__bfloat162float(h0), l1=v.y-__bfloat162float(h1),
              l2=v.z-__bfloat162float(h2), l3=v.w-__bfloat162float(h3);
        u32 off = (u32)(row*144 + c4*8);
        sts64(dh + off, pack2(h0,h1), pack2(h2,h3));
        sts64(dl + off, pack2(__float2bfloat16_rn(l0),__float2bfloat16_rn(l1)),
                        pack2(__float2bfloat16_rn(l2),__float2bfloat16_rn(l3)));
    }
}
// copy 64x64 bf16 tile (row stride 'stride' elems) -> [64][72]  (128 threads)
__device__ __forceinline__ void copy_bt(u32 dst, const __nv_bfloat16* __restrict__ src, int stride, int t){
    #pragma unroll
    for (int i = 0; i < 4; ++i){
        int e = t + i*128;
        int row = e >> 3, k8 = e & 7;
        uint4 v = *(const uint4*)(src + (size_t)row*stride + k8*8);
        sts128(dst + (u32)(row*144 + k8*16), v);
    }
}
// store one fp32 value split hi/lo into bf16 tiles at (row, col)
__device__ __forceinline__ void put_split(u32 th, u32 tl, int row, int col, float x){
    u32 off = (u32)(row*144 + col*2);
    __nv_bfloat16 h = __float2bfloat16_rn(x);
    float lo = x - __bfloat162float(h);
    sts16(th + off, __bfloat16_as_ushort(h));
    sts16(tl + off, __bfloat16_as_ushort(__float2bfloat16_rn(lo)));
}

// ---------------- prepA: w2s, invm, Gram partials (parallel over k-chunks) ----------------
__global__ __launch_bounds__(256) void prepA_kernel(const float* __restrict__ W1,
                                                    const float* __restrict__ W2,
                                                    const float* __restrict__ mass){
    int b = blockIdx.x, t = threadIdx.x;
    if (b == 0){
        __shared__ float red[4][64];
        int row = t & 63, part = t >> 6;
        const float* src = W2 + (size_t)row*DIM + part*256;
        float s = 0.f;
        #pragma unroll 8
        for (int i = 0; i < 64; ++i){
            float4 v = *(const float4*)(src + i*4);
            s += v.x + v.y + v.z + v.w;
        }
        red[part][row] = s;
        for (int i = t; i < DIM; i += 256) g_invm[i] = 1.0f / mass[i];
        __syncthreads();
        if (part == 0) g_w2s[row] = red[0][row] + red[1][row] + red[2][row] + red[3][row];
    } else {
        // blocks 1..32: (variant, kc) Gram partial: out[64][64] over K=64
        __shared__ float X[64*68];
        __shared__ float Y[64*68];
        int bb = b - 1;
        int variant = bb >> 4;           // 0: Gq partial, 1: Gm partial
        int kc = (bb & 15) * 64;
        for (int e = t; e < 4096; e += 256){
            int k = e >> 6, i = e & 63;
            X[k*68 + i] = W1[(size_t)(kc + k)*HID + i];
            float y;
            if (variant == 0) y = W1[(size_t)(DIM + kc + k)*HID + i];
            else              y = W1[(size_t)(kc + k)*HID + i] / mass[kc + k];
            Y[k*68 + i] = y;
        }
        __syncthreads();
        int i4 = (t & 15) * 4, j4 = (t >> 4) * 4;
        float acc[4][4] = {};
        #pragma unroll 8
        for (int k = 0; k < 64; ++k){
            float4 xv = *(const float4*)(X + k*68 + i4);
            float4 yv = *(const float4*)(Y + k*68 + j4);
            acc[0][0] = fmaf(xv.x, yv.x, acc[0][0]); acc[0][1] = fmaf(xv.x, yv.y, acc[0][1]);
            acc[0][2] = fmaf(xv.x, yv.z, acc[0][2]); acc[0][3] = fmaf(xv.x, yv.w, acc[0][3]);
            acc[1][0] = fmaf(xv.y, yv.x, acc[1][0]); acc[1][1] = fmaf(xv.y, yv.y, acc[1][1]);
            acc[1][2] = fmaf(xv.y, yv.z, acc[1][2]); acc[1][3] = fmaf(xv.y, yv.w, acc[1][3]);
            acc[2][0] = fmaf(xv.z, yv.x, acc[2][0]); acc[2][1] = fmaf(xv.z, yv.y, acc[2][1]);
            acc[2][2] = fmaf(xv.z, yv.z, acc[2][2]); acc[2][3] = fmaf(xv.z, yv.w, acc[2][3]);
            acc[3][0] = fmaf(xv.w, yv.x, acc[3][0]); acc[3][1] = fmaf(xv.w, yv.y, acc[3][1]);
            acc[3][2] = fmaf(xv.w, yv.z, acc[3][2]); acc[3][3] = fmaf(xv.w, yv.w, acc[3][3]);
        }
        float* dst = g_part + bb*4096;
        #pragma unroll
        for (int ii = 0; ii < 4; ++ii)
            #pragma unroll
            for (int jj = 0; jj < 4; ++jj)
                dst[(i4+ii)*64 + j4+jj] = acc[ii][jj];
    }
}

// ---------------- prepB: fixed-order reduction of Gram partials ----------------
__global__ __launch_bounds__(256) void prepB_kernel(){
    int variant = blockIdx.x, t = threadIdx.x;
    float* dst = variant ? g_Gm : g_Gq;
    for (int e = t; e < 4096; e += 256){
        float s = 0.f;
        #pragma unroll
        for (int c = 0; c < 16; ++c)
            s += g_part[(variant*16 + c)*4096 + e];
        dst[e] = s;
    }
}

// ---------------- prep2: bf16 hi/lo splits ----------------
__device__ __forceinline__ void split_st(__nv_bfloat16* H, __nv_bfloat16* L, int i, float x){
    __nv_bfloat16 h = __float2bfloat16_rn(x);
    H[i] = h;
    L[i] = __float2bfloat16_rn(x - __bfloat162float(h));
}
__global__ __launch_bounds__(256) void prep2_kernel(const float* __restrict__ W1,
                                                    const float* __restrict__ W2,
                                                    const float* __restrict__ dtp){
    float dt = dt_of(dtp), hdt = 0.5f*dt;
    int g = blockIdx.x*256 + threadIdx.x;
    int S = gridDim.x*256;
    for (int idx = g; idx < HID*DIM; idx += S){
        int j = idx >> 10, k = idx & 1023;
        float x = W1[k*HID + j];
        split_st(g_W1qT_h,  g_W1qT_l,  idx, x);
        split_st(g_W1pT_h,  g_W1pT_l,  idx, W1[(DIM + k)*HID + j]);
        split_st(g_W1qmT_h, g_W1qmT_l, idx, x * g_invm[k]);
    }
    for (int idx = g; idx < DIM*HID; idx += S){
        int d = idx >> 6, j = idx & 63;
        split_st(g_W1qB_h, g_W1qB_l, idx, W1[d*HID + j]);
        split_st(g_W2TB_h, g_W2TB_l, idx, W2[(size_t)j*DIM + d]);
    }
    for (int idx = g; idx < HID*HID; idx += S){
        int j2 = idx >> 6, j1 = idx & 63;
        float gq = g_Gq[j1*HID + j2];
        float gm = g_Gm[j1*HID + j2];
        split_st(g_G1T_h, g_G1T_l, idx, hdt*gq + dt*hdt*gm);
        split_st(g_GqT_h, g_GqT_l, idx, hdt*gq);
    }
}

// ---------------- smem layout (bytes) — 64-row CTA, X aliased with S1 ----------------
#define XH_   0u            // phase 1 staging (dead after phase 1)
#define XL_   9216u
#define S1H_  0u            // s1 tiles written phase 2 (alias X)
#define S1L_  9216u
#define B0H_  18432u
#define B0L_  27648u
#define B1H_  36864u
#define B1L_  46080u
#define CTH_  55296u
#define CTL_  64512u
#define ETH_  73728u
#define ETL_  82944u
#define CB1_  92160u
#define CWS_  92416u
// f32 stage buffers [64][68], alias B0/B1 (dead between gemms within a dc step)
#define STA_  18432u
#define STB_  35840u
#define SMEM_TOTAL 92672

// ---------------- mega kernel: 64 rows per CTA, 128 threads, 2 CTAs/SM ----------------
__global__ __launch_bounds__(128, 2) void mega(const float* __restrict__ q,
                                               const float* __restrict__ p,
                                               const float* __restrict__ b1,
                                               const float* __restrict__ dtp,
                                               float* __restrict__ out_q,
                                               float* __restrict__ out_p,
                                               float* __restrict__ out_e){
    extern __shared__ char smem[];
    u32 SB = s2u(smem);
    int t = threadIdx.x, w = t >> 5, l = t & 31;
    int mr = (w & 1) * 32;         // warp row base within 64
    int nc = (w >> 1) * 32;        // warp col base within 64
    int r0 = blockIdx.x * 64;
    float dt = dt_of(dtp), hdt = 0.5f*dt;

    if (t < 64){
        sts32f(SB + CB1_ + t*4, __ldg(b1 + t));
        sts32f(SB + CWS_ + t*4, g_w2s[t]);
    }

    // ================= phase 1: Z and V accumulation over K =================
    float accZ[2][4][4], accV[2][4][4];
    #pragma unroll
    for (int i = 0; i < 2; ++i)
        #pragma unroll
        for (int nb = 0; nb < 4; ++nb)
            #pragma unroll
            for (int c = 0; c < 4; ++c){ accZ[i][nb][c] = 0.f; accV[i][nb][c] = 0.f; }

    for (int ch = 0; ch < 32; ++ch){
        int is_p = (ch >= 16);
        int kk = (ch & 15) * 64;
        __syncthreads();
        conv_tile(SB+XH_, SB+XL_, (is_p ? p : q) + (size_t)r0*DIM + kk, t);
        if (!is_p){
            copy_bt(SB+B0H_, g_W1qT_h + kk, DIM, t);
            copy_bt(SB+B0L_, g_W1qT_l + kk, DIM, t);
        } else {
            copy_bt(SB+B0H_, g_W1pT_h + kk, DIM, t);
            copy_bt(SB+B0L_, g_W1pT_l + kk, DIM, t);
            copy_bt(SB+B1H_, g_W1qmT_h + kk, DIM, t);
            copy_bt(SB+B1L_, g_W1qmT_l + kk, DIM, t);
        }
        __syncthreads();
        if (!is_p){
            gemmK64(accZ, SB+XH_, SB+XL_, SB+B0H_, SB+B0L_, mr, nc, l);
        } else {
            gemmK64_dualB(accZ, accV, SB+XH_, SB+XL_,
                          SB+B0H_, SB+B0L_, SB+B1H_, SB+B1L_, mr, nc, l);
        }
    }
    __syncthreads();   // phase-1 gemms done reading X region before S1 overwrites it

    // ================= phase 2: z1, s1 =================
    float z1r[2][4][4], z2r[2][4][4];
    #pragma unroll
    for (int i = 0; i < 2; ++i)
        #pragma unroll
        for (int nb = 0; nb < 4; ++nb){
            int colb = nc + nb*8 + 2*(l & 3);
            #pragma unroll
            for (int c = 0; c < 4; ++c){
                int col = colb + (c & 1);
                int row = mr + i*16 + (l >> 2) + 8*(c >> 1);
                float z1 = accZ[i][nb][c] + ldsf(SB + CB1_ + col*4);
                float ws = ldsf(SB + CWS_ + col*4);
                z1r[i][nb][c] = z1;
                z2r[i][nb][c] = fmaf(dt, accV[i][nb][c], z1);   // z1 + dt*v (corr pending)
                put_split(SB+S1H_, SB+S1L_, row, col, dgelu_f(z1)*ws);
            }
        }
    // Gram tiles: B0 = G1T (hdt*Gq + dt*hdt*Gm), B1 = GqT (hdt*Gq)
    copy_bt(SB+B0H_, g_G1T_h, 64, t);
    copy_bt(SB+B0L_, g_G1T_l, 64, t);
    copy_bt(SB+B1H_, g_GqT_h, 64, t);
    copy_bt(SB+B1L_, g_GqT_l, 64, t);
    __syncthreads();

    // ================= phase 3: corr = s1@G1 ; z2, s2 =================
    {
        float cr[2][4][4] = {};
        gemmK64(cr, SB+S1H_, SB+S1L_, SB+B0H_, SB+B0L_, mr, nc, l);
        #pragma unroll
        for (int i = 0; i < 2; ++i)
            #pragma unroll
            for (int nb = 0; nb < 4; ++nb){
                int colb = nc + nb*8 + 2*(l & 3);
                #pragma unroll
                for (int c = 0; c < 4; ++c){
                    int col = colb + (c & 1);
                    int row = mr + i*16 + (l >> 2) + 8*(c >> 1);
                    float z2 = z2r[i][nb][c] - cr[i][nb][c];
                    z2r[i][nb][c] = z2;
                    float ws = ldsf(SB + CWS_ + col*4);
                    put_split(SB+CTH_, SB+CTL_, row, col, dgelu_f(z2)*ws);   // s2
                }
            }
    }
    __syncthreads();

    // ================= phase 4: c3 = s2@(hdt*Gq) ; E, C =================
    {
        float c3[2][4][4] = {};
        gemmK64(c3, SB+CTH_, SB+CTL_, SB+B1H_, SB+B1L_, mr, nc, l);
        __syncthreads();   // everyone done reading CT before overwrite
        #pragma unroll
        for (int i = 0; i < 2; ++i)
            #pragma unroll
            for (int nb = 0; nb < 4; ++nb){
                int colb = nc + nb*8 + 2*(l & 3);
                #pragma unroll
                for (int c = 0; c < 4; ++c){
                    int col = colb + (c & 1);
                    int row = mr + i*16 + (l >> 2) + 8*(c >> 1);
                    float z1 = z1r[i][nb][c];
                    float z2 = z2r[i][nb][c];
                    float z3 = z2 - c3[i][nb][c];
                    float ws = ldsf(SB + CWS_ + col*4);
                    put_split(SB+ETH_, SB+ETL_, row, col, gelu_f(z1) - gelu_f(z3));       // E
                    put_split(SB+CTH_, SB+CTL_, row, col, (dgelu_f(z1) + dgelu_f(z2))*ws); // C
                }
            }
    }

    // ================= phase 5: d-loop =================
    for (int dc = 0; dc < 16; ++dc){
        int d0 = dc * 64;
        __syncthreads();
        copy_bt(SB+B0H_, g_W1qB_h + (size_t)d0*HID, HID, t);
        copy_bt(SB+B0L_, g_W1qB_l + (size_t)d0*HID, HID, t);
        copy_bt(SB+B1H_, g_W2TB_h + (size_t)d0*HID, HID, t);
        copy_bt(SB+B1L_, g_W2TB_l + (size_t)d0*HID, HID, t);
        __syncthreads();

        float aq[2][4][4] = {}, cc[2][4][4] = {};
        gemmK64_dualA(aq, cc, SB+S1H_, SB+S1L_, SB+CTH_, SB+CTL_,
                      SB+B0H_, SB+B0L_, mr, nc, l);
        float ec[2][4][4] = {};
        gemmK64(ec, SB+ETH_, SB+ETL_, SB+B1H_, SB+B1L_, mr, nc, l);
        __syncthreads();   // B tiles dead; stage buffers may overwrite them

        // stage aq -> STA, cc -> STB (f32 [64][68])
        #pragma unroll
        for (int i = 0; i < 2; ++i)
            #pragma unroll
            for (int nb = 0; nb < 4; ++nb){
                int col = nc + nb*8 + 2*(l & 3);
                #pragma unroll
                for (int h = 0; h < 2; ++h){
                    int row = mr + i*16 + (l >> 2) + 8*h;
                    u32 so = (u32)(row*68 + col)*4u;
                    sts64f(SB + STA_ + so, aq[i][nb][2*h], aq[i][nb][2*h+1]);
                    sts64f(SB + STB_ + so, cc[i][nb][2*h], cc[i][nb][2*h+1]);
                }
            }
        __syncthreads();

        // coalesced epilogue: out_q, out_p
        #pragma unroll
        for (int it = 0; it < 8; ++it){
            int e = t + it*128;
            int row = e >> 4, c4 = e & 15;
            u32 so = (u32)(row*68 + c4*4)*4u;
            float4 a4 = lds128f(SB + STA_ + so);
            float4 c4v = lds128f(SB + STB_ + so);
            size_t off = (size_t)(r0 + row)*DIM + d0 + c4*4;
            float4 qv = *(const float4*)(q + off);
            float4 pv = *(const float4*)(p + off);
            float4 iv = *(const float4*)(g_invm + d0 + c4*4);
            float4 qn, pn;
            qn.x = qv.x + dt*iv.x*(pv.x - hdt*a4.x);
            qn.y = qv.y + dt*iv.y*(pv.y - hdt*a4.y);
            qn.z = qv.z + dt*iv.z*(pv.z - hdt*a4.z);
            qn.w = qv.w + dt*iv.w*(pv.w - hdt*a4.w);
            pn.x = pv.x - hdt*c4v.x;
            pn.y = pv.y - hdt*c4v.y;
            pn.z = pv.z - hdt*c4v.z;
            pn.w = pv.w - hdt*c4v.w;
            *(float4*)(out_q + off) = qn;
            *(float4*)(out_p + off) = pn;
        }
        __syncthreads();

        // stage ec -> STA
        #pragma unroll
        for (int i = 0; i < 2; ++i)
            #pragma unroll
            for (int nb = 0; nb < 4; ++nb){
                int col = nc + nb*8 + 2*(l & 3);
                #pragma unroll
                for (int h = 0; h < 2; ++h){
                    int row = mr + i*16 + (l >> 2) + 8*h;
                    u32 so = (u32)(row*68 + col)*4u;
                    sts64f(SB + STA_ + so, ec[i][nb][2*h], ec[i][nb][2*h+1]);
                }
            }
        __syncthreads();

        // coalesced epilogue: out_e
        #pragma unroll
        for (int it = 0; it < 8; ++it){
            int e = t + it*128;
            int row = e >> 4, c4 = e & 15;
            float4 e4 = lds128f(SB + STA_ + (u32)(row*68 + c4*4)*4u);
            size_t off = (size_t)(r0 + row)*DIM + d0 + c4*4;
            float4 ev;
            ev.x = fabsf(e4.x); ev.y = fabsf(e4.y);
            ev.z = fabsf(e4.z); ev.w = fabsf(e4.w);
            *(float4*)(out_e + off) = ev;
        }
    }
}

// ---------------- launch ----------------
extern "C" void kernel_launch(void* const* d_in, const int* in_sizes, int n_in,
                              void* d_out, int out_size){
    const float* q    = (const float*)d_in[0];
    const float* p    = (const float*)d_in[1];
    const float* W1   = (const float*)d_in[2];
    const float* b1   = (const float*)d_in[3];
    const float* W2   = (const float*)d_in[4];
    const float* mass = (const float*)d_in[6];
    const float* dtp  = (const float*)d_in[7];
    float* out_q = (float*)d_out;
    float* out_p = out_q + (size_t)BB*DIM;
    float* out_e = out_p + (size_t)BB*DIM;

    cudaFuncSetAttribute(mega, cudaFuncAttributeMaxDynamicSharedMemorySize, SMEM_TOTAL);

    prepA_kernel<<<33, 256>>>(W1, W2, mass);
    prepB_kernel<<<2, 256>>>();
    prep2_kernel<<<64, 256>>>(W1, W2, dtp);
    mega<<<BB/64, 128, SMEM_TOTAL>>>(q, p, b1, dtp, out_q, out_p, out_e);
}

// round 14
// speedup vs baseline: 1.0627x; 1.0627x over previous
#include <cuda_runtime.h>
#include <cuda_bf16.h>
#include <math.h>
#include <stdint.h>

#define BB   16384
#define DIM  1024
#define HID  64

typedef uint32_t u32;

// ---------------- device scratch (no allocations allowed) ----------------
__device__ float g_w2s[HID];
__device__ float g_invm[DIM];
__device__ float g_Gq[HID*HID];   // W1q^T W1p
__device__ float g_Gm[HID*HID];   // W1q^T diag(1/m) W1q
__device__ float g_part[32*4096]; // Gram partials (variant,kc)

// bf16 hi/lo pre-split weights
__device__ __align__(16) __nv_bfloat16 g_W1qT_h[HID*DIM],  g_W1qT_l[HID*DIM];   // [j][k]
__device__ __align__(16) __nv_bfloat16 g_W1pT_h[HID*DIM],  g_W1pT_l[HID*DIM];   // [j][k]
__device__ __align__(16) __nv_bfloat16 g_W1qmT_h[HID*DIM], g_W1qmT_l[HID*DIM];  // [j][k] invm folded
__device__ __align__(16) __nv_bfloat16 g_W1qB_h[DIM*HID],  g_W1qB_l[DIM*HID];   // [d][j]
__device__ __align__(16) __nv_bfloat16 g_W2TB_h[DIM*HID],  g_W2TB_l[DIM*HID];   // [d][j] = W2[j][d]
__device__ __align__(16) __nv_bfloat16 g_G1T_h[HID*HID],   g_G1T_l[HID*HID];    // [j2][j1] hdt*Gq+dt*hdt*Gm
__device__ __align__(16) __nv_bfloat16 g_GqT_h[HID*HID],   g_GqT_l[HID*HID];    // [j2][j1] hdt*Gq

// ---------------- scalar helpers ----------------
__device__ __forceinline__ float dt_of(const float* dtp){
    float x = __ldg(dtp);
    return 1.0f/(1.0f + expf(-x));
}
__device__ __forceinline__ float gelu_f(float x){
    return x * 0.5f * (1.0f + erff(x * 0.70710678118654752440f));
}
__device__ __forceinline__ float dgelu_f(float x){
    float cdf = 0.5f * (1.0f + erff(x * 0.70710678118654752440f));
    float pdf = 0.39894228040143267794f * expf(-0.5f * x * x);
    return cdf + x * pdf;
}

// ---------------- smem primitives ----------------
__device__ __forceinline__ u32 s2u(const void* p){
    u32 a;
    asm("{ .reg .u64 t; cvta.to.shared.u64 t, %1; cvt.u32.u64 %0, t; }" : "=r"(a) : "l"(p));
    return a;
}
__device__ __forceinline__ void sts16(u32 a, unsigned short v){ asm volatile("st.shared.b16 [%0], %1;" :: "r"(a), "h"(v)); }
__device__ __forceinline__ void sts32f(u32 a, float v){ asm volatile("st.shared.f32 [%0], %1;" :: "r"(a), "f"(v)); }
__device__ __forceinline__ void sts64(u32 a, u32 x, u32 y){ asm volatile("st.shared.v2.b32 [%0], {%1,%2};" :: "r"(a), "r"(x), "r"(y)); }
__device__ __forceinline__ void sts128(u32 a, uint4 v){ asm volatile("st.shared.v4.b32 [%0], {%1,%2,%3,%4};" :: "r"(a), "r"(v.x), "r"(v.y), "r"(v.z), "r"(v.w)); }
__device__ __forceinline__ float ldsf(u32 a){ float v; asm volatile("ld.shared.f32 %0, [%1];" : "=f"(v) : "r"(a)); return v; }
__device__ __forceinline__ float4 lds128f(u32 a){ float4 v; asm volatile("ld.shared.v4.f32 {%0,%1,%2,%3}, [%4];" : "=f"(v.x),"=f"(v.y),"=f"(v.z),"=f"(v.w) : "r"(a)); return v; }

__device__ __forceinline__ u32 pack2(__nv_bfloat16 a, __nv_bfloat16 b){
    return (u32)__bfloat16_as_ushort(a) | ((u32)__bfloat16_as_ushort(b) << 16);
}

// ---------------- cp.async ----------------
#define CPA_COMMIT() asm volatile("cp.async.commit_group;" ::: "memory")
#define CPA_WAIT1()  asm volatile("cp.async.wait_group 1;" ::: "memory")
#define CPA_WAIT0()  asm volatile("cp.async.wait_group 0;" ::: "memory")
// async copy of a 64x64 fp32 chunk (row stride DIM) -> smem [64][68] f32 (272B rows)
__device__ __forceinline__ void cpa_x(u32 dst, const float* __restrict__ src, int t){
    #pragma unroll
    for (int i = 0; i < 8; ++i){
        int e = t + i*128;
        int row = e >> 4, c4 = e & 15;
        asm volatile("cp.async.cg.shared.global [%0], [%1], 16;"
            :: "r"(dst + (u32)(row*272 + c4*16)), "l"(src + (size_t)row*DIM + c4*4));
    }
}

// ---------------- MMA primitives ----------------
// A-tile fragment (m16 x k16) from [row][k] layout, row stride 144 bytes
__device__ __forceinline__ void ldA(u32 base, int rowbase, int ks, int l, u32 a[4]){
    u32 addr = base + (u32)(rowbase + (l & 15))*144u + (u32)(((l >> 4)*8 + ks*16)*2);
    asm volatile("ldmatrix.sync.aligned.m8n8.x4.shared.b16 {%0,%1,%2,%3}, [%4];"
        : "=r"(a[0]), "=r"(a[1]), "=r"(a[2]), "=r"(a[3]) : "r"(addr));
}
// B-tile fragment (n8 x k16) from [n][k] layout, row stride 144 bytes
__device__ __forceinline__ void ldB(u32 base, int nrow, int ks, int l, u32 b[2]){
    u32 addr = base + (u32)(nrow + (l & 7))*144u + (u32)(((((l >> 3) & 1)*8) + ks*16)*2);
    asm volatile("ldmatrix.sync.aligned.m8n8.x2.shared.b16 {%0,%1}, [%2];"
        : "=r"(b[0]), "=r"(b[1]) : "r"(addr));
}
__device__ __forceinline__ void mm(float c[4], const u32 a[4], const u32 b[2]){
    asm volatile("mma.sync.aligned.m16n8k16.row.col.f32.bf16.bf16.f32 "
        "{%0,%1,%2,%3}, {%4,%5,%6,%7}, {%8,%9}, {%0,%1,%2,%3};"
        : "+f"(c[0]), "+f"(c[1]), "+f"(c[2]), "+f"(c[3])
        : "r"(a[0]), "r"(a[1]), "r"(a[2]), "r"(a[3]), "r"(b[0]), "r"(b[1]));
}

// K=64 3-term GEMM: acc[2][4][4] += A(64x64 hi/lo) x B(64x64 hi/lo)^T
// warp tile: 32 rows (mr) x 32 cols (nc)
__device__ __forceinline__ void gemmK64(float acc[2][4][4], u32 AH, u32 AL,
                                        u32 BH, u32 BL, int mr, int nc, int l){
    #pragma unroll
    for (int ks = 0; ks < 4; ++ks){
        u32 ah[2][4], al[2][4];
        ldA(AH, mr,     ks, l, ah[0]);
        ldA(AH, mr+16,  ks, l, ah[1]);
        ldA(AL, mr,     ks, l, al[0]);
        ldA(AL, mr+16,  ks, l, al[1]);
        #pragma unroll
        for (int nb = 0; nb < 4; ++nb){
            u32 bh[2], bl[2];
            ldB(BH, nc + nb*8, ks, l, bh);
            ldB(BL, nc + nb*8, ks, l, bl);
            #pragma unroll
            for (int i = 0; i < 2; ++i){
                mm(acc[i][nb], ah[i], bh);
                mm(acc[i][nb], ah[i], bl);
                mm(acc[i][nb], al[i], bh);
            }
        }
    }
}
// dual-B variant: accZ += A x B0, accV += A x B1 (shared A fragments)
__device__ __forceinline__ void gemmK64_dualB(float accZ[2][4][4], float accV[2][4][4],
                                              u32 AH, u32 AL,
                                              u32 B0H, u32 B0L, u32 B1H, u32 B1L,
                                              int mr, int nc, int l){
    #pragma unroll
    for (int ks = 0; ks < 4; ++ks){
        u32 ah[2][4], al[2][4];
        ldA(AH, mr,     ks, l, ah[0]);
        ldA(AH, mr+16,  ks, l, ah[1]);
        ldA(AL, mr,     ks, l, al[0]);
        ldA(AL, mr+16,  ks, l, al[1]);
        #pragma unroll
        for (int nb = 0; nb < 4; ++nb){
            u32 bh[2], bl[2], ch[2], cl[2];
            ldB(B0H, nc + nb*8, ks, l, bh);
            ldB(B0L, nc + nb*8, ks, l, bl);
            ldB(B1H, nc + nb*8, ks, l, ch);
            ldB(B1L, nc + nb*8, ks, l, cl);
            #pragma unroll
            for (int i = 0; i < 2; ++i){
                mm(accZ[i][nb], ah[i], bh);
                mm(accZ[i][nb], ah[i], bl);
                mm(accZ[i][nb], al[i], bh);
                mm(accV[i][nb], ah[i], ch);
                mm(accV[i][nb], ah[i], cl);
                mm(accV[i][nb], al[i], ch);
            }
        }
    }
}
// dual-A variant: accA += A1 x B, accC += A2 x B (shared B fragments)
__device__ __forceinline__ void gemmK64_dualA(float accA[2][4][4], float accC[2][4][4],
                                              u32 A1H, u32 A1L, u32 A2H, u32 A2L,
                                              u32 BH, u32 BL, int mr, int nc, int l){
    #pragma unroll
    for (int ks = 0; ks < 4; ++ks){
        u32 ah1[2][4], al1[2][4], ah2[2][4], al2[2][4];
        ldA(A1H, mr,     ks, l, ah1[0]);
        ldA(A1H, mr+16,  ks, l, ah1[1]);
        ldA(A1L, mr,     ks, l, al1[0]);
        ldA(A1L, mr+16,  ks, l, al1[1]);
        ldA(A2H, mr,     ks, l, ah2[0]);
        ldA(A2H, mr+16,  ks, l, ah2[1]);
        ldA(A2L, mr,     ks, l, al2[0]);
        ldA(A2L, mr+16,  ks, l, al2[1]);
        #pragma unroll
        for (int nb = 0; nb < 4; ++nb){
            u32 bh[2], bl[2];
            ldB(BH, nc + nb*8, ks, l, bh);
            ldB(BL, nc + nb*8, ks, l, bl);
            #pragma unroll
            for (int i = 0; i < 2; ++i){
                mm(accA[i][nb], ah1[i], bh);
                mm(accA[i][nb], ah1[i], bl);
                mm(accA[i][nb], al1[i], bh);
                mm(accC[i][nb], ah2[i], bh);
                mm(accC[i][nb], ah2[i], bl);
                mm(accC[i][nb], al2[i], bh);
            }
        }
    }
}

// convert 64x64 fp32 from SMEM stage [64][68]f32 -> hi/lo bf16 tiles [64][72]  (128 threads)
__device__ __forceinline__ void conv_tile_s(u32 dh, u32 dl, u32 srcS, int t){
    #pragma unroll
    for (int i = 0; i < 8; ++i){
        int e = t + i*128;
        int row = e >> 4, c4 = e & 15;
        float4 v = lds128f(srcS + (u32)(row*272 + c4*16));
        __nv_bfloat16 h0=__float2bfloat16_rn(v.x), h1=__float2bfloat16_rn(v.y),
                      h2=__float2bfloat16_rn(v.z), h3=__float2bfloat16_rn(v.w);
        float l0=v.x-__bfloat162float(h0), l1=v.y-__bfloat162float(h1),
              l2=v.z-__bfloat162float(h2), l3=v.w-__bfloat162float(h3);
        u32 off = (u32)(row*144 + c4*8);
        sts64(dh + off, pack2(h0,h1), pack2(h2,h3));
        sts64(dl + off, pack2(__float2bfloat16_rn(l0),__float2bfloat16_rn(l1)),
                        pack2(__float2bfloat16_rn(l2),__float2bfloat16_rn(l3)));
    }
}
// copy 64x64 bf16 tile (row stride 'stride' elems) -> [64][72]  (128 threads)
__device__ __forceinline__ void copy_bt(u32 dst, const __nv_bfloat16* __restrict__ src, int stride, int t){
    #pragma unroll
    for (int i = 0; i < 4; ++i){
        int e = t + i*128;
        int row = e >> 3, k8 = e & 7;
        uint4 v = *(const uint4*)(src + (size_t)row*stride + k8*8);
        sts128(dst + (u32)(row*144 + k8*16), v);
    }
}
// store one fp32 value split hi/lo into bf16 tiles at (row, col)
__device__ __forceinline__ void put_split(u32 th, u32 tl, int row, int col, float x){
    u32 off = (u32)(row*144 + col*2);
    __nv_bfloat16 h = __float2bfloat16_rn(x);
    float lo = x - __bfloat162float(h);
    sts16(th + off, __bfloat16_as_ushort(h));
    sts16(tl + off, __bfloat16_as_ushort(__float2bfloat16_rn(lo)));
}

// ---------------- prepA: w2s, invm, Gram partials (parallel over k-chunks) ----------------
__global__ __launch_bounds__(256) void prepA_kernel(const float* __restrict__ W1,
                                                    const float* __restrict__ W2,
                                                    const float* __restrict__ mass){
    int b = blockIdx.x, t = threadIdx.x;
    if (b == 0){
        __shared__ float red[4][64];
        int row = t & 63, part = t >> 6;
        const float* src = W2 + (size_t)row*DIM + part*256;
        float s = 0.f;
        #pragma unroll 8
        for (int i = 0; i < 64; ++i){
            float4 v = *(const float4*)(src + i*4);
            s += v.x + v.y + v.z + v.w;
        }
        red[part][row] = s;
        for (int i = t; i < DIM; i += 256) g_invm[i] = 1.0f / mass[i];
        __syncthreads();
        if (part == 0) g_w2s[row] = red[0][row] + red[1][row] + red[2][row] + red[3][row];
    } else {
        // blocks 1..32: (variant, kc) Gram partial: out[64][64] over K=64
        __shared__ float X[64*68];
        __shared__ float Y[64*68];
        int bb = b - 1;
        int variant = bb >> 4;           // 0: Gq partial, 1: Gm partial
        int kc = (bb & 15) * 64;
        for (int e = t; e < 4096; e += 256){
            int k = e >> 6, i = e & 63;
            X[k*68 + i] = W1[(size_t)(kc + k)*HID + i];
            float y;
            if (variant == 0) y = W1[(size_t)(DIM + kc + k)*HID + i];
            else              y = W1[(size_t)(kc + k)*HID + i] / mass[kc + k];
            Y[k*68 + i] = y;
        }
        __syncthreads();
        int i4 = (t & 15) * 4, j4 = (t >> 4) * 4;
        float acc[4][4] = {};
        #pragma unroll 8
        for (int k = 0; k < 64; ++k){
            float4 xv = *(const float4*)(X + k*68 + i4);
            float4 yv = *(const float4*)(Y + k*68 + j4);
            acc[0][0] = fmaf(xv.x, yv.x, acc[0][0]); acc[0][1] = fmaf(xv.x, yv.y, acc[0][1]);
            acc[0][2] = fmaf(xv.x, yv.z, acc[0][2]); acc[0][3] = fmaf(xv.x, yv.w, acc[0][3]);
            acc[1][0] = fmaf(xv.y, yv.x, acc[1][0]); acc[1][1] = fmaf(xv.y, yv.y, acc[1][1]);
            acc[1][2] = fmaf(xv.y, yv.z, acc[1][2]); acc[1][3] = fmaf(xv.y, yv.w, acc[1][3]);
            acc[2][0] = fmaf(xv.z, yv.x, acc[2][0]); acc[2][1] = fmaf(xv.z, yv.y, acc[2][1]);
            acc[2][2] = fmaf(xv.z, yv.z, acc[2][2]); acc[2][3] = fmaf(xv.z, yv.w, acc[2][3]);
            acc[3][0] = fmaf(xv.w, yv.x, acc[3][0]); acc[3][1] = fmaf(xv.w, yv.y, acc[3][1]);
            acc[3][2] = fmaf(xv.w, yv.z, acc[3][2]); acc[3][3] = fmaf(xv.w, yv.w, acc[3][3]);
        }
        float* dst = g_part + bb*4096;
        #pragma unroll
        for (int ii = 0; ii < 4; ++ii)
            #pragma unroll
            for (int jj = 0; jj < 4; ++jj)
                dst[(i4+ii)*64 + j4+jj] = acc[ii][jj];
    }
}

// ---------------- prepB: fixed-order reduction of Gram partials ----------------
__global__ __launch_bounds__(256) void prepB_kernel(){
    int variant = blockIdx.x, t = threadIdx.x;
    float* dst = variant ? g_Gm : g_Gq;
    for (int e = t; e < 4096; e += 256){
        float s = 0.f;
        #pragma unroll
        for (int c = 0; c < 16; ++c)
            s += g_part[(variant*16 + c)*4096 + e];
        dst[e] = s;
    }
}

// ---------------- prep2: bf16 hi/lo splits ----------------
__device__ __forceinline__ void split_st(__nv_bfloat16* H, __nv_bfloat16* L, int i, float x){
    __nv_bfloat16 h = __float2bfloat16_rn(x);
    H[i] = h;
    L[i] = __float2bfloat16_rn(x - __bfloat162float(h));
}
__global__ __launch_bounds__(256) void prep2_kernel(const float* __restrict__ W1,
                                                    const float* __restrict__ W2,
                                                    const float* __restrict__ dtp){
    float dt = dt_of(dtp), hdt = 0.5f*dt;
    int g = blockIdx.x*256 + threadIdx.x;
    int S = gridDim.x*256;
    for (int idx = g; idx < HID*DIM; idx += S){
        int j = idx >> 10, k = idx & 1023;
        float x = W1[k*HID + j];
        split_st(g_W1qT_h,  g_W1qT_l,  idx, x);
        split_st(g_W1pT_h,  g_W1pT_l,  idx, W1[(DIM + k)*HID + j]);
        split_st(g_W1qmT_h, g_W1qmT_l, idx, x * g_invm[k]);
    }
    for (int idx = g; idx < DIM*HID; idx += S){
        int d = idx >> 6, j = idx & 63;
        split_st(g_W1qB_h, g_W1qB_l, idx, W1[d*HID + j]);
        split_st(g_W2TB_h, g_W2TB_l, idx, W2[(size_t)j*DIM + d]);
    }
    for (int idx = g; idx < HID*HID; idx += S){
        int j2 = idx >> 6, j1 = idx & 63;
        float gq = g_Gq[j1*HID + j2];
        float gm = g_Gm[j1*HID + j2];
        split_st(g_G1T_h, g_G1T_l, idx, hdt*gq + dt*hdt*gm);
        split_st(g_GqT_h, g_GqT_l, idx, hdt*gq);
    }
}

// ---------------- smem layout (bytes) — 64-row CTA, X aliased with S1 ----------------
#define XH_   0u            // phase 1 staging (dead after phase 1)
#define XL_   9216u
#define S1H_  0u            // s1 tiles written phase 2 (alias X)
#define S1L_  9216u
#define B0H_  18432u
#define B0L_  27648u
#define B1H_  36864u
#define B1L_  46080u
#define CTH_  55296u
#define CTL_  64512u
#define ETH_  73728u
#define ETL_  82944u
// phase-1 f32 X ping-pong stages, alias CT/ET (dead in phase 1): [64][68]f32 = 17408B
#define XF0_  55296u
#define XF1_  72704u
#define CB1_  92160u
#define CWS_  92416u
#define SMEM_TOTAL 92672

// ---------------- mega kernel: 64 rows per CTA, 128 threads, 2 CTAs/SM ----------------
__global__ __launch_bounds__(128, 2) void mega(const float* __restrict__ q,
                                               const float* __restrict__ p,
                                               const float* __restrict__ b1,
                                               const float* __restrict__ dtp,
                                               float* __restrict__ out_q,
                                               float* __restrict__ out_p,
                                               float* __restrict__ out_e){
    extern __shared__ char smem[];
    u32 SB = s2u(smem);
    int t = threadIdx.x, w = t >> 5, l = t & 31;
    int mr = (w & 1) * 32;         // warp row base within 64
    int nc = (w >> 1) * 32;        // warp col base within 64
    int r0 = blockIdx.x * 64;
    float dt = dt_of(dtp), hdt = 0.5f*dt;

    if (t < 64){
        sts32f(SB + CB1_ + t*4, __ldg(b1 + t));
        sts32f(SB + CWS_ + t*4, g_w2s[t]);
    }

    // ================= phase 1: Z and V accumulation over K (cp.async X pipeline) =================
    float accZ[2][4][4], accV[2][4][4];
    #pragma unroll
    for (int i = 0; i < 2; ++i)
        #pragma unroll
        for (int nb = 0; nb < 4; ++nb)
            #pragma unroll
            for (int c = 0; c < 4; ++c){ accZ[i][nb][c] = 0.f; accV[i][nb][c] = 0.f; }

    cpa_x(SB+XF0_, q + (size_t)r0*DIM, t);
    CPA_COMMIT();

    for (int ch = 0; ch < 32; ++ch){
        int is_p = (ch >= 16);
        int kk = (ch & 15) * 64;
        __syncthreads();                  // prev gemm done with XH/XL + B tiles
        if (ch+1 < 32){
            int np = ((ch+1) >= 16), nk = ((ch+1) & 15)*64;
            cpa_x(SB + (((ch+1) & 1) ? XF1_ : XF0_),
                  (np ? p : q) + (size_t)r0*DIM + nk, t);
            CPA_COMMIT();
        }
        if (!is_p){
            copy_bt(SB+B0H_, g_W1qT_h + kk, DIM, t);
            copy_bt(SB+B0L_, g_W1qT_l + kk, DIM, t);
        } else {
            copy_bt(SB+B0H_, g_W1pT_h + kk, DIM, t);
            copy_bt(SB+B0L_, g_W1pT_l + kk, DIM, t);
            copy_bt(SB+B1H_, g_W1qmT_h + kk, DIM, t);
            copy_bt(SB+B1L_, g_W1qmT_l + kk, DIM, t);
        }
        if (ch+1 < 32) CPA_WAIT1(); else CPA_WAIT0();
        conv_tile_s(SB+XH_, SB+XL_, SB + ((ch & 1) ? XF1_ : XF0_), t);
        __syncthreads();
        if (!is_p){
            gemmK64(accZ, SB+XH_, SB+XL_, SB+B0H_, SB+B0L_, mr, nc, l);
        } else {
            gemmK64_dualB(accZ, accV, SB+XH_, SB+XL_,
                          SB+B0H_, SB+B0L_, SB+B1H_, SB+B1L_, mr, nc, l);
        }
    }
    __syncthreads();   // phase-1 gemms done reading X region before S1 overwrites it

    // ================= phase 2: z1, s1 =================
    float z1r[2][4][4], z2r[2][4][4];
    #pragma unroll
    for (int i = 0; i < 2; ++i)
        #pragma unroll
        for (int nb = 0; nb < 4; ++nb){
            int colb = nc + nb*8 + 2*(l & 3);
            #pragma unroll
            for (int c = 0; c < 4; ++c){
                int col = colb + (c & 1);
                int row = mr + i*16 + (l >> 2) + 8*(c >> 1);
                float z1 = accZ[i][nb][c] + ldsf(SB + CB1_ + col*4);
                float ws = ldsf(SB + CWS_ + col*4);
                z1r[i][nb][c] = z1;
                z2r[i][nb][c] = fmaf(dt, accV[i][nb][c], z1);   // z1 + dt*v (corr pending)
                put_split(SB+S1H_, SB+S1L_, row, col, dgelu_f(z1)*ws);
            }
        }
    // Gram tiles: B0 = G1T (hdt*Gq + dt*hdt*Gm), B1 = GqT (hdt*Gq)
    copy_bt(SB+B0H_, g_G1T_h, 64, t);
    copy_bt(SB+B0L_, g_G1T_l, 64, t);
    copy_bt(SB+B1H_, g_GqT_h, 64, t);
    copy_bt(SB+B1L_, g_GqT_l, 64, t);
    __syncthreads();

    // ================= phase 3: corr = s1@G1 ; z2, s2 =================
    {
        float cr[2][4][4] = {};
        gemmK64(cr, SB+S1H_, SB+S1L_, SB+B0H_, SB+B0L_, mr, nc, l);
        #pragma unroll
        for (int i = 0; i < 2; ++i)
            #pragma unroll
            for (int nb = 0; nb < 4; ++nb){
                int colb = nc + nb*8 + 2*(l & 3);
                #pragma unroll
                for (int c = 0; c < 4; ++c){
                    int col = colb + (c & 1);
                    int row = mr + i*16 + (l >> 2) + 8*(c >> 1);
                    float z2 = z2r[i][nb][c] - cr[i][nb][c];
                    z2r[i][nb][c] = z2;
                    float ws = ldsf(SB + CWS_ + col*4);
                    put_split(SB+CTH_, SB+CTL_, row, col, dgelu_f(z2)*ws);   // s2
                }
            }
    }
    __syncthreads();

    // ================= phase 4: c3 = s2@(hdt*Gq) ; E, C =================
    {
        float c3[2][4][4] = {};
        gemmK64(c3, SB+CTH_, SB+CTL_, SB+B1H_, SB+B1L_, mr, nc, l);
        __syncthreads();   // everyone done reading CT before overwrite
        #pragma unroll
        for (int i = 0; i < 2; ++i)
            #pragma unroll
            for (int nb = 0; nb < 4; ++nb){
                int colb = nc + nb*8 + 2*(l & 3);
                #pragma unroll
                for (int c = 0; c < 4; ++c){
                    int col = colb + (c & 1);
                    int row = mr + i*16 + (l >> 2) + 8*(c >> 1);
                    float z1 = z1r[i][nb][c];
                    float z2 = z2r[i][nb][c];
                    float z3 = z2 - c3[i][nb][c];
                    float ws = ldsf(SB + CWS_ + col*4);
                    put_split(SB+ETH_, SB+ETL_, row, col, gelu_f(z1) - gelu_f(z3));       // E
                    put_split(SB+CTH_, SB+CTL_, row, col, (dgelu_f(z1) + dgelu_f(z2))*ws); // C
                }
            }
    }

    // ================= phase 5: d-loop (R12 direct epilogue) =================
    for (int dc = 0; dc < 16; ++dc){
        int d0 = dc * 64;
        __syncthreads();
        copy_bt(SB+B0H_, g_W1qB_h + (size_t)d0*HID, HID, t);
        copy_bt(SB+B0L_, g_W1qB_l + (size_t)d0*HID, HID, t);
        copy_bt(SB+B1H_, g_W2TB_h + (size_t)d0*HID, HID, t);
        copy_bt(SB+B1L_, g_W2TB_l + (size_t)d0*HID, HID, t);
        __syncthreads();

        float aq[2][4][4] = {}, cc[2][4][4] = {};
        gemmK64_dualA(aq, cc, SB+S1H_, SB+S1L_, SB+CTH_, SB+CTL_,
                      SB+B0H_, SB+B0L_, mr, nc, l);
        #pragma unroll
        for (int i = 0; i < 2; ++i)
            #pragma unroll
            for (int nb = 0; nb < 4; ++nb){
                int col = nc + nb*8 + 2*(l & 3);
                #pragma unroll
                for (int h = 0; h < 2; ++h){
                    int row = mr + i*16 + (l >> 2) + 8*h;
                    size_t off = (size_t)(r0 + row)*DIM + d0 + col;
                    float2 qv = *(const float2*)(q + off);
                    float2 pv = *(const float2*)(p + off);
                    float2 iv = *(const float2*)(g_invm + d0 + col);
                    float a0 = aq[i][nb][2*h], a1 = aq[i][nb][2*h+1];
                    float c0 = cc[i][nb][2*h], c1 = cc[i][nb][2*h+1];
                    float2 qn, pn;
                    qn.x = qv.x + dt*iv.x*(pv.x - hdt*a0);
                    qn.y = qv.y + dt*iv.y*(pv.y - hdt*a1);
                    pn.x = pv.x - hdt*c0;
                    pn.y = pv.y - hdt*c1;
                    *(float2*)(out_q + off) = qn;
                    *(float2*)(out_p + off) = pn;
                }
            }

        float ec[2][4][4] = {};
        gemmK64(ec, SB+ETH_, SB+ETL_, SB+B1H_, SB+B1L_, mr, nc, l);
        #pragma unroll
        for (int i = 0; i < 2; ++i)
            #pragma unroll
            for (int nb = 0; nb < 4; ++nb){
                int col = nc + nb*8 + 2*(l & 3);
                #pragma unroll
                for (int h = 0; h < 2; ++h){
                    int row = mr + i*16 + (l >> 2) + 8*h;
                    size_t off = (size_t)(r0 + row)*DIM + d0 + col;
                    float2 ev;
                    ev.x = fabsf(ec[i][nb][2*h]);
                    ev.y = fabsf(ec[i][nb][2*h+1]);
                    *(float2*)(out_e + off) = ev;
                }
            }
    }
}

// ---------------- launch ----------------
extern "C" void kernel_launch(void* const* d_in, const int* in_sizes, int n_in,
                              void* d_out, int out_size){
    const float* q    = (const float*)d_in[0];
    const float* p    = (const float*)d_in[1];
    const float* W1   = (const float*)d_in[2];
    const float* b1   = (const float*)d_in[3];
    const float* W2   = (const float*)d_in[4];
    const float* mass = (const float*)d_in[6];
    const float* dtp  = (const float*)d_in[7];
    float* out_q = (float*)d_out;
    float* out_p = out_q + (size_t)BB*DIM;
    float* out_e = out_p + (size_t)BB*DIM;

    cudaFuncSetAttribute(mega, cudaFuncAttributeMaxDynamicSharedMemorySize, SMEM_TOTAL);

    prepA_kernel<<<33, 256>>>(W1, W2, mass);
    prepB_kernel<<<2, 256>>>();
    prep2_kernel<<<64, 256>>>(W1, W2, dtp);
    mega<<<BB/64, 128, SMEM_TOTAL>>>(q, p, b1, dtp, out_q, out_p, out_e);
}

// round 15
// speedup vs baseline: 1.1379x; 1.0708x over previous
#include <cuda_runtime.h>
#include <cuda_bf16.h>
#include <math.h>
#include <stdint.h>

#define BB   16384
#define DIM  1024
#define HID  64

typedef uint32_t u32;

// ---------------- device scratch (no allocations allowed) ----------------
__device__ float g_w2s[HID];
__device__ float g_invm[DIM];
__device__ float g_Gq[HID*HID];   // W1q^T W1p
__device__ float g_Gm[HID*HID];   // W1q^T diag(1/m) W1q
__device__ float g_part[32*4096]; // Gram partials (variant,kc)

// bf16 hi/lo pre-split weights
__device__ __align__(16) __nv_bfloat16 g_W1qT_h[HID*DIM],  g_W1qT_l[HID*DIM];   // [j][k]
__device__ __align__(16) __nv_bfloat16 g_W1pT_h[HID*DIM],  g_W1pT_l[HID*DIM];   // [j][k]
__device__ __align__(16) __nv_bfloat16 g_W1qmT_h[HID*DIM], g_W1qmT_l[HID*DIM];  // [j][k] invm folded
__device__ __align__(16) __nv_bfloat16 g_W1qB_h[DIM*HID],  g_W1qB_l[DIM*HID];   // [d][j]
__device__ __align__(16) __nv_bfloat16 g_W2TB_h[DIM*HID],  g_W2TB_l[DIM*HID];   // [d][j] = W2[j][d]
__device__ __align__(16) __nv_bfloat16 g_G1T_h[HID*HID],   g_G1T_l[HID*HID];    // [j2][j1] hdt*Gq+dt*hdt*Gm
__device__ __align__(16) __nv_bfloat16 g_GqT_h[HID*HID],   g_GqT_l[HID*HID];    // [j2][j1] hdt*Gq

// ---------------- scalar helpers ----------------
__device__ __forceinline__ float dt_of(const float* dtp){
    float x = __ldg(dtp);
    return 1.0f/(1.0f + expf(-x));
}
__device__ __forceinline__ float gelu_f(float x){
    return x * 0.5f * (1.0f + erff(x * 0.70710678118654752440f));
}
__device__ __forceinline__ float dgelu_f(float x){
    float cdf = 0.5f * (1.0f + erff(x * 0.70710678118654752440f));
    float pdf = 0.39894228040143267794f * expf(-0.5f * x * x);
    return cdf + x * pdf;
}

// ---------------- smem primitives ----------------
__device__ __forceinline__ u32 s2u(const void* p){
    u32 a;
    asm("{ .reg .u64 t; cvta.to.shared.u64 t, %1; cvt.u32.u64 %0, t; }" : "=r"(a) : "l"(p));
    return a;
}
__device__ __forceinline__ void sts16(u32 a, unsigned short v){ asm volatile("st.shared.b16 [%0], %1;" :: "r"(a), "h"(v)); }
__device__ __forceinline__ void sts32f(u32 a, float v){ asm volatile("st.shared.f32 [%0], %1;" :: "r"(a), "f"(v)); }
__device__ __forceinline__ void sts64(u32 a, u32 x, u32 y){ asm volatile("st.shared.v2.b32 [%0], {%1,%2};" :: "r"(a), "r"(x), "r"(y)); }
__device__ __forceinline__ void sts128(u32 a, uint4 v){ asm volatile("st.shared.v4.b32 [%0], {%1,%2,%3,%4};" :: "r"(a), "r"(v.x), "r"(v.y), "r"(v.z), "r"(v.w)); }
__device__ __forceinline__ float ldsf(u32 a){ float v; asm volatile("ld.shared.f32 %0, [%1];" : "=f"(v) : "r"(a)); return v; }

__device__ __forceinline__ u32 pack2(__nv_bfloat16 a, __nv_bfloat16 b){
    return (u32)__bfloat16_as_ushort(a) | ((u32)__bfloat16_as_ushort(b) << 16);
}

// ---------------- MMA primitives ----------------
// A-tile fragment (m16 x k16) from [row][k] layout, row stride 144 bytes
__device__ __forceinline__ void ldA(u32 base, int rowbase, int ks, int l, u32 a[4]){
    u32 addr = base + (u32)(rowbase + (l & 15))*144u + (u32)(((l >> 4)*8 + ks*16)*2);
    asm volatile("ldmatrix.sync.aligned.m8n8.x4.shared.b16 {%0,%1,%2,%3}, [%4];"
        : "=r"(a[0]), "=r"(a[1]), "=r"(a[2]), "=r"(a[3]) : "r"(addr));
}
// B-tile fragment (n8 x k16) from [n][k] layout, row stride 144 bytes
__device__ __forceinline__ void ldB(u32 base, int nrow, int ks, int l, u32 b[2]){
    u32 addr = base + (u32)(nrow + (l & 7))*144u + (u32)(((((l >> 3) & 1)*8) + ks*16)*2);
    asm volatile("ldmatrix.sync.aligned.m8n8.x2.shared.b16 {%0,%1}, [%2];"
        : "=r"(b[0]), "=r"(b[1]) : "r"(addr));
}
__device__ __forceinline__ void mm(float c[4], const u32 a[4], const u32 b[2]){
    asm volatile("mma.sync.aligned.m16n8k16.row.col.f32.bf16.bf16.f32 "
        "{%0,%1,%2,%3}, {%4,%5,%6,%7}, {%8,%9}, {%0,%1,%2,%3};"
        : "+f"(c[0]), "+f"(c[1]), "+f"(c[2]), "+f"(c[3])
        : "r"(a[0]), "r"(a[1]), "r"(a[2]), "r"(a[3]), "r"(b[0]), "r"(b[1]));
}

// K=64 3-term GEMM: acc[2][4][4] += A(64x64 hi/lo) x B(64x64 hi/lo)^T
// warp tile: 32 rows (mr) x 32 cols (nc)
__device__ __forceinline__ void gemmK64(float acc[2][4][4], u32 AH, u32 AL,
                                        u32 BH, u32 BL, int mr, int nc, int l){
    #pragma unroll
    for (int ks = 0; ks < 4; ++ks){
        u32 ah[2][4], al[2][4];
        ldA(AH, mr,     ks, l, ah[0]);
        ldA(AH, mr+16,  ks, l, ah[1]);
        ldA(AL, mr,     ks, l, al[0]);
        ldA(AL, mr+16,  ks, l, al[1]);
        #pragma unroll
        for (int nb = 0; nb < 4; ++nb){
            u32 bh[2], bl[2];
            ldB(BH, nc + nb*8, ks, l, bh);
            ldB(BL, nc + nb*8, ks, l, bl);
            #pragma unroll
            for (int i = 0; i < 2; ++i){
                mm(acc[i][nb], ah[i], bh);
                mm(acc[i][nb], ah[i], bl);
                mm(acc[i][nb], al[i], bh);
            }
        }
    }
}
// dual-B variant: accZ += A x B0, accV += A x B1 (shared A fragments)
__device__ __forceinline__ void gemmK64_dualB(float accZ[2][4][4], float accV[2][4][4],
                                              u32 AH, u32 AL,
                                              u32 B0H, u32 B0L, u32 B1H, u32 B1L,
                                              int mr, int nc, int l){
    #pragma unroll
    for (int ks = 0; ks < 4; ++ks){
        u32 ah[2][4], al[2][4];
        ldA(AH, mr,     ks, l, ah[0]);
        ldA(AH, mr+16,  ks, l, ah[1]);
        ldA(AL, mr,     ks, l, al[0]);
        ldA(AL, mr+16,  ks, l, al[1]);
        #pragma unroll
        for (int nb = 0; nb < 4; ++nb){
            u32 bh[2], bl[2], ch[2], cl[2];
            ldB(B0H, nc + nb*8, ks, l, bh);
            ldB(B0L, nc + nb*8, ks, l, bl);
            ldB(B1H, nc + nb*8, ks, l, ch);
            ldB(B1L, nc + nb*8, ks, l, cl);
            #pragma unroll
            for (int i = 0; i < 2; ++i){
                mm(accZ[i][nb], ah[i], bh);
                mm(accZ[i][nb], ah[i], bl);
                mm(accZ[i][nb], al[i], bh);
                mm(accV[i][nb], ah[i], ch);
                mm(accV[i][nb], ah[i], cl);
                mm(accV[i][nb], al[i], ch);
            }
        }
    }
}
// dual-A variant: accA += A1 x B, accC += A2 x B (shared B fragments)
__device__ __forceinline__ void gemmK64_dualA(float accA[2][4][4], float accC[2][4][4],
                                              u32 A1H, u32 A1L, u32 A2H, u32 A2L,
                                              u32 BH, u32 BL, int mr, int nc, int l){
    #pragma unroll
    for (int ks = 0; ks < 4; ++ks){
        u32 ah1[2][4], al1[2][4], ah2[2][4], al2[2][4];
        ldA(A1H, mr,     ks, l, ah1[0]);
        ldA(A1H, mr+16,  ks, l, ah1[1]);
        ldA(A1L, mr,     ks, l, al1[0]);
        ldA(A1L, mr+16,  ks, l, al1[1]);
        ldA(A2H, mr,     ks, l, ah2[0]);
        ldA(A2H, mr+16,  ks, l, ah2[1]);
        ldA(A2L, mr,     ks, l, al2[0]);
        ldA(A2L, mr+16,  ks, l, al2[1]);
        #pragma unroll
        for (int nb = 0; nb < 4; ++nb){
            u32 bh[2], bl[2];
            ldB(BH, nc + nb*8, ks, l, bh);
            ldB(BL, nc + nb*8, ks, l, bl);
            #pragma unroll
            for (int i = 0; i < 2; ++i){
                mm(accA[i][nb], ah1[i], bh);
                mm(accA[i][nb], ah1[i], bl);
                mm(accA[i][nb], al1[i], bh);
                mm(accC[i][nb], ah2[i], bh);
                mm(accC[i][nb], ah2[i], bl);
                mm(accC[i][nb], al2[i], bh);
            }
        }
    }
}

// convert 64x64 fp32 chunk (row stride DIM) -> hi/lo bf16 tiles [64][72]  (128 threads)
__device__ __forceinline__ void conv_tile(u32 dh, u32 dl, const float* __restrict__ src, int t){
    #pragma unroll
    for (int i = 0; i < 8; ++i){
        int e = t + i*128;
        int row = e >> 4, c4 = e & 15;
        float4 v = *(const float4*)(src + (size_t)row*DIM + c4*4);
        __nv_bfloat16 h0=__float2bfloat16_rn(v.x), h1=__float2bfloat16_rn(v.y),
                      h2=__float2bfloat16_rn(v.z), h3=__float2bfloat16_rn(v.w);
        float l0=v.x-__bfloat162float(h0), l1=v.y-__bfloat162float(h1),
              l2=v.z-__bfloat162float(h2), l3=v.w-__bfloat162float(h3);
        u32 off = (u32)(row*144 + c4*8);
        sts64(dh + off, pack2(h0,h1), pack2(h2,h3));
        sts64(dl + off, pack2(__float2bfloat16_rn(l0),__float2bfloat16_rn(l1)),
                        pack2(__float2bfloat16_rn(l2),__float2bfloat16_rn(l3)));
    }
}
// copy 64x64 bf16 tile (row stride 'stride' elems) -> [64][72]  (128 threads)
__device__ __forceinline__ void copy_bt(u32 dst, const __nv_bfloat16* __restrict__ src, int stride, int t){
    #pragma unroll
    for (int i = 0; i < 4; ++i){
        int e = t + i*128;
        int row = e >> 3, k8 = e & 7;
        uint4 v = *(const uint4*)(src + (size_t)row*stride + k8*8);
        sts128(dst + (u32)(row*144 + k8*16), v);
    }
}
// store one fp32 value split hi/lo into bf16 tiles at (row, col)
__device__ __forceinline__ void put_split(u32 th, u32 tl, int row, int col, float x){
    u32 off = (u32)(row*144 + col*2);
    __nv_bfloat16 h = __float2bfloat16_rn(x);
    float lo = x - __bfloat162float(h);
    sts16(th + off, __bfloat16_as_ushort(h));
    sts16(tl + off, __bfloat16_as_ushort(__float2bfloat16_rn(lo)));
}

// ---------------- prepA: w2s, invm, Gram partials (parallel over k-chunks) ----------------
__global__ __launch_bounds__(256) void prepA_kernel(const float* __restrict__ W1,
                                                    const float* __restrict__ W2,
                                                    const float* __restrict__ mass){
    int b = blockIdx.x, t = threadIdx.x;
    if (b == 0){
        __shared__ float red[4][64];
        int row = t & 63, part = t >> 6;
        const float* src = W2 + (size_t)row*DIM + part*256;
        float s = 0.f;
        #pragma unroll 8
        for (int i = 0; i < 64; ++i){
            float4 v = *(const float4*)(src + i*4);
            s += v.x + v.y + v.z + v.w;
        }
        red[part][row] = s;
        for (int i = t; i < DIM; i += 256) g_invm[i] = 1.0f / mass[i];
        __syncthreads();
        if (part == 0) g_w2s[row] = red[0][row] + red[1][row] + red[2][row] + red[3][row];
    } else {
        // blocks 1..32: (variant, kc) Gram partial: out[64][64] over K=64
        __shared__ float X[64*68];
        __shared__ float Y[64*68];
        int bb = b - 1;
        int variant = bb >> 4;           // 0: Gq partial, 1: Gm partial
        int kc = (bb & 15) * 64;
        for (int e = t; e < 4096; e += 256){
            int k = e >> 6, i = e & 63;
            X[k*68 + i] = W1[(size_t)(kc + k)*HID + i];
            float y;
            if (variant == 0) y = W1[(size_t)(DIM + kc + k)*HID + i];
            else              y = W1[(size_t)(kc + k)*HID + i] / mass[kc + k];
            Y[k*68 + i] = y;
        }
        __syncthreads();
        int i4 = (t & 15) * 4, j4 = (t >> 4) * 4;
        float acc[4][4] = {};
        #pragma unroll 8
        for (int k = 0; k < 64; ++k){
            float4 xv = *(const float4*)(X + k*68 + i4);
            float4 yv = *(const float4*)(Y + k*68 + j4);
            acc[0][0] = fmaf(xv.x, yv.x, acc[0][0]); acc[0][1] = fmaf(xv.x, yv.y, acc[0][1]);
            acc[0][2] = fmaf(xv.x, yv.z, acc[0][2]); acc[0][3] = fmaf(xv.x, yv.w, acc[0][3]);
            acc[1][0] = fmaf(xv.y, yv.x, acc[1][0]); acc[1][1] = fmaf(xv.y, yv.y, acc[1][1]);
            acc[1][2] = fmaf(xv.y, yv.z, acc[1][2]); acc[1][3] = fmaf(xv.y, yv.w, acc[1][3]);
            acc[2][0] = fmaf(xv.z, yv.x, acc[2][0]); acc[2][1] = fmaf(xv.z, yv.y, acc[2][1]);
            acc[2][2] = fmaf(xv.z, yv.z, acc[2][2]); acc[2][3] = fmaf(xv.z, yv.w, acc[2][3]);
            acc[3][0] = fmaf(xv.w, yv.x, acc[3][0]); acc[3][1] = fmaf(xv.w, yv.y, acc[3][1]);
            acc[3][2] = fmaf(xv.w, yv.z, acc[3][2]); acc[3][3] = fmaf(xv.w, yv.w, acc[3][3]);
        }
        float* dst = g_part + bb*4096;
        #pragma unroll
        for (int ii = 0; ii < 4; ++ii)
            #pragma unroll
            for (int jj = 0; jj < 4; ++jj)
                dst[(i4+ii)*64 + j4+jj] = acc[ii][jj];
    }
}

// ---------------- prepB: fixed-order reduction of Gram partials ----------------
__global__ __launch_bounds__(256) void prepB_kernel(){
    int variant = blockIdx.x, t = threadIdx.x;
    float* dst = variant ? g_Gm : g_Gq;
    for (int e = t; e < 4096; e += 256){
        float s = 0.f;
        #pragma unroll
        for (int c = 0; c < 16; ++c)
            s += g_part[(variant*16 + c)*4096 + e];
        dst[e] = s;
    }
}

// ---------------- prep2: bf16 hi/lo splits ----------------
__device__ __forceinline__ void split_st(__nv_bfloat16* H, __nv_bfloat16* L, int i, float x){
    __nv_bfloat16 h = __float2bfloat16_rn(x);
    H[i] = h;
    L[i] = __float2bfloat16_rn(x - __bfloat162float(h));
}
__global__ __launch_bounds__(256) void prep2_kernel(const float* __restrict__ W1,
                                                    const float* __restrict__ W2,
                                                    const float* __restrict__ dtp){
    float dt = dt_of(dtp), hdt = 0.5f*dt;
    int g = blockIdx.x*256 + threadIdx.x;
    int S = gridDim.x*256;
    for (int idx = g; idx < HID*DIM; idx += S){
        int j = idx >> 10, k = idx & 1023;
        float x = W1[k*HID + j];
        split_st(g_W1qT_h,  g_W1qT_l,  idx, x);
        split_st(g_W1pT_h,  g_W1pT_l,  idx, W1[(DIM + k)*HID + j]);
        split_st(g_W1qmT_h, g_W1qmT_l, idx, x * g_invm[k]);
    }
    for (int idx = g; idx < DIM*HID; idx += S){
        int d = idx >> 6, j = idx & 63;
        split_st(g_W1qB_h, g_W1qB_l, idx, W1[d*HID + j]);
        split_st(g_W2TB_h, g_W2TB_l, idx, W2[(size_t)j*DIM + d]);
    }
    for (int idx = g; idx < HID*HID; idx += S){
        int j2 = idx >> 6, j1 = idx & 63;
        float gq = g_Gq[j1*HID + j2];
        float gm = g_Gm[j1*HID + j2];
        split_st(g_G1T_h, g_G1T_l, idx, hdt*gq + dt*hdt*gm);
        split_st(g_GqT_h, g_GqT_l, idx, hdt*gq);
    }
}

// ---------------- smem layout (bytes) — 64-row CTA, K=128 phase-1 pairs ----------------
// Phase 1:  XA (even chunk X hi/lo) | XB (odd chunk X hi/lo) | W0..W3 (B tile slots)
// Phase 2+: S1 = XA region, B0 = XB region, B1 = W0, CT = W1, ET = W2 (W3 idle)
#define XA_   0u
#define XB_   18432u
#define W0_   36864u
#define W1_   55296u
#define W2_   73728u
#define W3_   92160u
#define S1H_  0u
#define S1L_  9216u
#define B0H_  18432u
#define B0L_  27648u
#define B1H_  36864u
#define B1L_  46080u
#define CTH_  55296u
#define CTL_  64512u
#define ETH_  73728u
#define ETL_  82944u
#define CB1_  110592u
#define CWS_  110848u
#define SMEM_TOTAL 111104

// ---------------- mega kernel: 64 rows per CTA, 128 threads, 2 CTAs/SM ----------------
__global__ __launch_bounds__(128, 2) void mega(const float* __restrict__ q,
                                               const float* __restrict__ p,
                                               const float* __restrict__ b1,
                                               const float* __restrict__ dtp,
                                               float* __restrict__ out_q,
                                               float* __restrict__ out_p,
                                               float* __restrict__ out_e){
    extern __shared__ char smem[];
    u32 SB = s2u(smem);
    int t = threadIdx.x, w = t >> 5, l = t & 31;
    int mr = (w & 1) * 32;         // warp row base within 64
    int nc = (w >> 1) * 32;        // warp col base within 64
    int r0 = blockIdx.x * 64;
    float dt = dt_of(dtp), hdt = 0.5f*dt;

    if (t < 64){
        sts32f(SB + CB1_ + t*4, __ldg(b1 + t));
        sts32f(SB + CWS_ + t*4, g_w2s[t]);
    }

    // ================= phase 1: Z and V, two K=64 chunks per sync pair =================
    float accZ[2][4][4], accV[2][4][4];
    #pragma unroll
    for (int i = 0; i < 2; ++i)
        #pragma unroll
        for (int nb = 0; nb < 4; ++nb)
            #pragma unroll
            for (int c = 0; c < 4; ++c){ accZ[i][nb][c] = 0.f; accV[i][nb][c] = 0.f; }

    for (int pr = 0; pr < 16; ++pr){
        int is_p = (pr >= 8);
        int kk = (pr & 7) * 128;           // covers [kk, kk+128)
        const float* src = (is_p ? p : q) + (size_t)r0*DIM;
        __syncthreads();
        conv_tile(SB+XA_, SB+XA_+9216u, src + kk,      t);
        conv_tile(SB+XB_, SB+XB_+9216u, src + kk + 64, t);
        if (!is_p){
            copy_bt(SB+W0_,        g_W1qT_h + kk,      DIM, t);
            copy_bt(SB+W0_+9216u,  g_W1qT_l + kk,      DIM, t);
            copy_bt(SB+W1_,        g_W1qT_h + kk + 64, DIM, t);
            copy_bt(SB+W1_+9216u,  g_W1qT_l + kk + 64, DIM, t);
        } else {
            copy_bt(SB+W0_,        g_W1pT_h + kk,       DIM, t);
            copy_bt(SB+W0_+9216u,  g_W1pT_l + kk,       DIM, t);
            copy_bt(SB+W1_,        g_W1qmT_h + kk,      DIM, t);
            copy_bt(SB+W1_+9216u,  g_W1qmT_l + kk,      DIM, t);
            copy_bt(SB+W2_,        g_W1pT_h + kk + 64,  DIM, t);
            copy_bt(SB+W2_+9216u,  g_W1pT_l + kk + 64,  DIM, t);
            copy_bt(SB+W3_,        g_W1qmT_h + kk + 64, DIM, t);
            copy_bt(SB+W3_+9216u,  g_W1qmT_l + kk + 64, DIM, t);
        }
        __syncthreads();
        if (!is_p){
            gemmK64(accZ, SB+XA_, SB+XA_+9216u, SB+W0_, SB+W0_+9216u, mr, nc, l);
            gemmK64(accZ, SB+XB_, SB+XB_+9216u, SB+W1_, SB+W1_+9216u, mr, nc, l);
        } else {
            gemmK64_dualB(accZ, accV, SB+XA_, SB+XA_+9216u,
                          SB+W0_, SB+W0_+9216u, SB+W1_, SB+W1_+9216u, mr, nc, l);
            gemmK64_dualB(accZ, accV, SB+XB_, SB+XB_+9216u,
                          SB+W2_, SB+W2_+9216u, SB+W3_, SB+W3_+9216u, mr, nc, l);
        }
    }
    __syncthreads();   // phase-1 gemms done reading XA/XB before S1/B0 overwrite them

    // ================= phase 2: z1, s1 =================
    float z1r[2][4][4], z2r[2][4][4];
    #pragma unroll
    for (int i = 0; i < 2; ++i)
        #pragma unroll
        for (int nb = 0; nb < 4; ++nb){
            int colb = nc + nb*8 + 2*(l & 3);
            #pragma unroll
            for (int c = 0; c < 4; ++c){
                int col = colb + (c & 1);
                int row = mr + i*16 + (l >> 2) + 8*(c >> 1);
                float z1 = accZ[i][nb][c] + ldsf(SB + CB1_ + col*4);
                float ws = ldsf(SB + CWS_ + col*4);
                z1r[i][nb][c] = z1;
                z2r[i][nb][c] = fmaf(dt, accV[i][nb][c], z1);   // z1 + dt*v (corr pending)
                put_split(SB+S1H_, SB+S1L_, row, col, dgelu_f(z1)*ws);
            }
        }
    // Gram tiles: B0 = G1T (hdt*Gq + dt*hdt*Gm), B1 = GqT (hdt*Gq)
    copy_bt(SB+B0H_, g_G1T_h, 64, t);
    copy_bt(SB+B0L_, g_G1T_l, 64, t);
    copy_bt(SB+B1H_, g_GqT_h, 64, t);
    copy_bt(SB+B1L_, g_GqT_l, 64, t);
    __syncthreads();

    // ================= phase 3: corr = s1@G1 ; z2, s2 =================
    {
        float cr[2][4][4] = {};
        gemmK64(cr, SB+S1H_, SB+S1L_, SB+B0H_, SB+B0L_, mr, nc, l);
        #pragma unroll
        for (int i = 0; i < 2; ++i)
            #pragma unroll
            for (int nb = 0; nb < 4; ++nb){
                int colb = nc + nb*8 + 2*(l & 3);
                #pragma unroll
                for (int c = 0; c < 4; ++c){
                    int col = colb + (c & 1);
                    int row = mr + i*16 + (l >> 2) + 8*(c >> 1);
                    float z2 = z2r[i][nb][c] - cr[i][nb][c];
                    z2r[i][nb][c] = z2;
                    float ws = ldsf(SB + CWS_ + col*4);
                    put_split(SB+CTH_, SB+CTL_, row, col, dgelu_f(z2)*ws);   // s2
                }
            }
    }
    __syncthreads();

    // ================= phase 4: c3 = s2@(hdt*Gq) ; E, C =================
    {
        float c3[2][4][4] = {};
        gemmK64(c3, SB+CTH_, SB+CTL_, SB+B1H_, SB+B1L_, mr, nc, l);
        __syncthreads();   // everyone done reading CT before overwrite
        #pragma unroll
        for (int i = 0; i < 2; ++i)
            #pragma unroll
            for (int nb = 0; nb < 4; ++nb){
                int colb = nc + nb*8 + 2*(l & 3);
                #pragma unroll
                for (int c = 0; c < 4; ++c){
                    int col = colb + (c & 1);
                    int row = mr + i*16 + (l >> 2) + 8*(c >> 1);
                    float z1 = z1r[i][nb][c];
                    float z2 = z2r[i][nb][c];
                    float z3 = z2 - c3[i][nb][c];
                    float ws = ldsf(SB + CWS_ + col*4);
                    put_split(SB+ETH_, SB+ETL_, row, col, gelu_f(z1) - gelu_f(z3));       // E
                    put_split(SB+CTH_, SB+CTL_, row, col, (dgelu_f(z1) + dgelu_f(z2))*ws); // C
                }
            }
    }

    // ================= phase 5: d-loop (R12 direct epilogue) =================
    for (int dc = 0; dc < 16; ++dc){
        int d0 = dc * 64;
        __syncthreads();
        copy_bt(SB+B0H_, g_W1qB_h + (size_t)d0*HID, HID, t);
        copy_bt(SB+B0L_, g_W1qB_l + (size_t)d0*HID, HID, t);
        copy_bt(SB+B1H_, g_W2TB_h + (size_t)d0*HID, HID, t);
        copy_bt(SB+B1L_, g_W2TB_l + (size_t)d0*HID, HID, t);
        __syncthreads();

        float aq[2][4][4] = {}, cc[2][4][4] = {};
        gemmK64_dualA(aq, cc, SB+S1H_, SB+S1L_, SB+CTH_, SB+CTL_,
                      SB+B0H_, SB+B0L_, mr, nc, l);
        #pragma unroll
        for (int i = 0; i < 2; ++i)
            #pragma unroll
            for (int nb = 0; nb < 4; ++nb){
                int col = nc + nb*8 + 2*(l & 3);
                #pragma unroll
                for (int h = 0; h < 2; ++h){
                    int row = mr + i*16 + (l >> 2) + 8*h;
                    size_t off = (size_t)(r0 + row)*DIM + d0 + col;
                    float2 qv = *(const float2*)(q + off);
                    float2 pv = *(const float2*)(p + off);
                    float2 iv = *(const float2*)(g_invm + d0 + col);
                    float a0 = aq[i][nb][2*h], a1 = aq[i][nb][2*h+1];
                    float c0 = cc[i][nb][2*h], c1 = cc[i][nb][2*h+1];
                    float2 qn, pn;
                    qn.x = qv.x + dt*iv.x*(pv.x - hdt*a0);
                    qn.y = qv.y + dt*iv.y*(pv.y - hdt*a1);
                    pn.x = pv.x - hdt*c0;
                    pn.y = pv.y - hdt*c1;
                    *(float2*)(out_q + off) = qn;
                    *(float2*)(out_p + off) = pn;
                }
            }

        float ec[2][4][4] = {};
        gemmK64(ec, SB+ETH_, SB+ETL_, SB+B1H_, SB+B1L_, mr, nc, l);
        #pragma unroll
        for (int i = 0; i < 2; ++i)
            #pragma unroll
            for (int nb = 0; nb < 4; ++nb){
                int col = nc + nb*8 + 2*(l & 3);
                #pragma unroll
                for (int h = 0; h < 2; ++h){
                    int row = mr + i*16 + (l >> 2) + 8*h;
                    size_t off = (size_t)(r0 + row)*DIM + d0 + col;
                    float2 ev;
                    ev.x = fabsf(ec[i][nb][2*h]);
                    ev.y = fabsf(ec[i][nb][2*h+1]);
                    *(float2*)(out_e + off) = ev;
                }
            }
    }
}

// ---------------- launch ----------------
extern "C" void kernel_launch(void* const* d_in, const int* in_sizes, int n_in,
                              void* d_out, int out_size){
    const float* q    = (const float*)d_in[0];
    const float* p    = (const float*)d_in[1];
    const float* W1   = (const float*)d_in[2];
    const float* b1   = (const float*)d_in[3];
    const float* W2   = (const float*)d_in[4];
    const float* mass = (const float*)d_in[6];
    const float* dtp  = (const float*)d_in[7];
    float* out_q = (float*)d_out;
    float* out_p = out_q + (size_t)BB*DIM;
    float* out_e = out_p + (size_t)BB*DIM;

    cudaFuncSetAttribute(mega, cudaFuncAttributeMaxDynamicSharedMemorySize, SMEM_TOTAL);

    prepA_kernel<<<33, 256>>>(W1, W2, mass);
    prepB_kernel<<<2, 256>>>();
    prep2_kernel<<<64, 256>>>(W1, W2, dtp);
    mega<<<BB/64, 128, SMEM_TOTAL>>>(q, p, b1, dtp, out_q, out_p, out_e);
}

// round 16
// speedup vs baseline: 1.2480x; 1.0967x over previous
#include <cuda_runtime.h>
#include <cuda_bf16.h>
#include <math.h>
#include <stdint.h>

#define BB   16384
#define DIM  1024
#define HID  64

typedef uint32_t u32;

// ---------------- device scratch (no allocations allowed) ----------------
__device__ float g_w2s[HID];
__device__ float g_invm[DIM];
__device__ float g_Gq[HID*HID];   // W1q^T W1p
__device__ float g_Gm[HID*HID];   // W1q^T diag(1/m) W1q
__device__ float g_part[32*4096]; // Gram partials (variant,kc)

// bf16 hi/lo pre-split weights
__device__ __align__(16) __nv_bfloat16 g_W1qT_h[HID*DIM],  g_W1qT_l[HID*DIM];   // [j][k]
__device__ __align__(16) __nv_bfloat16 g_W1pT_h[HID*DIM],  g_W1pT_l[HID*DIM];   // [j][k]
__device__ __align__(16) __nv_bfloat16 g_W1qmT_h[HID*DIM], g_W1qmT_l[HID*DIM];  // [j][k] invm folded
__device__ __align__(16) __nv_bfloat16 g_W1qB_h[DIM*HID],  g_W1qB_l[DIM*HID];   // [d][j]
__device__ __align__(16) __nv_bfloat16 g_W2TB_h[DIM*HID],  g_W2TB_l[DIM*HID];   // [d][j] = W2[j][d]
__device__ __align__(16) __nv_bfloat16 g_G1T_h[HID*HID],   g_G1T_l[HID*HID];    // [j2][j1] hdt*Gq+dt*hdt*Gm
__device__ __align__(16) __nv_bfloat16 g_GqT_h[HID*HID],   g_GqT_l[HID*HID];    // [j2][j1] hdt*Gq

// ---------------- scalar helpers ----------------
__device__ __forceinline__ float dt_of(const float* dtp){
    float x = __ldg(dtp);
    return 1.0f/(1.0f + expf(-x));
}
__device__ __forceinline__ float gelu_f(float x){
    return x * 0.5f * (1.0f + erff(x * 0.70710678118654752440f));
}
__device__ __forceinline__ float dgelu_f(float x){
    float cdf = 0.5f * (1.0f + erff(x * 0.70710678118654752440f));
    float pdf = 0.39894228040143267794f * expf(-0.5f * x * x);
    return cdf + x * pdf;
}

// ---------------- smem primitives ----------------
__device__ __forceinline__ u32 s2u(const void* p){
    u32 a;
    asm("{ .reg .u64 t; cvta.to.shared.u64 t, %1; cvt.u32.u64 %0, t; }" : "=r"(a) : "l"(p));
    return a;
}
__device__ __forceinline__ void sts16(u32 a, unsigned short v){ asm volatile("st.shared.b16 [%0], %1;" :: "r"(a), "h"(v)); }
__device__ __forceinline__ void sts32f(u32 a, float v){ asm volatile("st.shared.f32 [%0], %1;" :: "r"(a), "f"(v)); }
__device__ __forceinline__ void sts64(u32 a, u32 x, u32 y){ asm volatile("st.shared.v2.b32 [%0], {%1,%2};" :: "r"(a), "r"(x), "r"(y)); }
__device__ __forceinline__ void sts128(u32 a, uint4 v){ asm volatile("st.shared.v4.b32 [%0], {%1,%2,%3,%4};" :: "r"(a), "r"(v.x), "r"(v.y), "r"(v.z), "r"(v.w)); }
__device__ __forceinline__ float ldsf(u32 a){ float v; asm volatile("ld.shared.f32 %0, [%1];" : "=f"(v) : "r"(a)); return v; }

__device__ __forceinline__ u32 pack2(__nv_bfloat16 a, __nv_bfloat16 b){
    return (u32)__bfloat16_as_ushort(a) | ((u32)__bfloat16_as_ushort(b) << 16);
}

// ---------------- MMA primitives ----------------
// A-tile fragment (m16 x k16) from [row][k] layout, row stride 144 bytes
__device__ __forceinline__ void ldA(u32 base, int rowbase, int ks, int l, u32 a[4]){
    u32 addr = base + (u32)(rowbase + (l & 15))*144u + (u32)(((l >> 4)*8 + ks*16)*2);
    asm volatile("ldmatrix.sync.aligned.m8n8.x4.shared.b16 {%0,%1,%2,%3}, [%4];"
        : "=r"(a[0]), "=r"(a[1]), "=r"(a[2]), "=r"(a[3]) : "r"(addr));
}
// B-tile fragment (n8 x k16) from [n][k] layout, row stride 144 bytes
__device__ __forceinline__ void ldB(u32 base, int nrow, int ks, int l, u32 b[2]){
    u32 addr = base + (u32)(nrow + (l & 7))*144u + (u32)(((((l >> 3) & 1)*8) + ks*16)*2);
    asm volatile("ldmatrix.sync.aligned.m8n8.x2.shared.b16 {%0,%1}, [%2];"
        : "=r"(b[0]), "=r"(b[1]) : "r"(addr));
}
__device__ __forceinline__ void mm(float c[4], const u32 a[4], const u32 b[2]){
    asm volatile("mma.sync.aligned.m16n8k16.row.col.f32.bf16.bf16.f32 "
        "{%0,%1,%2,%3}, {%4,%5,%6,%7}, {%8,%9}, {%0,%1,%2,%3};"
        : "+f"(c[0]), "+f"(c[1]), "+f"(c[2]), "+f"(c[3])
        : "r"(a[0]), "r"(a[1]), "r"(a[2]), "r"(a[3]), "r"(b[0]), "r"(b[1]));
}

// K=64 3-term GEMM: acc[2][4][4] += A(64x64 hi/lo) x B(64x64 hi/lo)^T
// warp tile: 32 rows (mr) x 32 cols (nc)
__device__ __forceinline__ void gemmK64(float acc[2][4][4], u32 AH, u32 AL,
                                        u32 BH, u32 BL, int mr, int nc, int l){
    #pragma unroll
    for (int ks = 0; ks < 4; ++ks){
        u32 ah[2][4], al[2][4];
        ldA(AH, mr,     ks, l, ah[0]);
        ldA(AH, mr+16,  ks, l, ah[1]);
        ldA(AL, mr,     ks, l, al[0]);
        ldA(AL, mr+16,  ks, l, al[1]);
        #pragma unroll
        for (int nb = 0; nb < 4; ++nb){
            u32 bh[2], bl[2];
            ldB(BH, nc + nb*8, ks, l, bh);
            ldB(BL, nc + nb*8, ks, l, bl);
            #pragma unroll
            for (int i = 0; i < 2; ++i){
                mm(acc[i][nb], ah[i], bh);
                mm(acc[i][nb], ah[i], bl);
                mm(acc[i][nb], al[i], bh);
            }
        }
    }
}
// dual-B variant: accZ += A x B0, accV += A x B1 (shared A fragments)
__device__ __forceinline__ void gemmK64_dualB(float accZ[2][4][4], float accV[2][4][4],
                                              u32 AH, u32 AL,
                                              u32 B0H, u32 B0L, u32 B1H, u32 B1L,
                                              int mr, int nc, int l){
    #pragma unroll
    for (int ks = 0; ks < 4; ++ks){
        u32 ah[2][4], al[2][4];
        ldA(AH, mr,     ks, l, ah[0]);
        ldA(AH, mr+16,  ks, l, ah[1]);
        ldA(AL, mr,     ks, l, al[0]);
        ldA(AL, mr+16,  ks, l, al[1]);
        #pragma unroll
        for (int nb = 0; nb < 4; ++nb){
            u32 bh[2], bl[2], ch[2], cl[2];
            ldB(B0H, nc + nb*8, ks, l, bh);
            ldB(B0L, nc + nb*8, ks, l, bl);
            ldB(B1H, nc + nb*8, ks, l, ch);
            ldB(B1L, nc + nb*8, ks, l, cl);
            #pragma unroll
            for (int i = 0; i < 2; ++i){
                mm(accZ[i][nb], ah[i], bh);
                mm(accZ[i][nb], ah[i], bl);
                mm(accZ[i][nb], al[i], bh);
                mm(accV[i][nb], ah[i], ch);
                mm(accV[i][nb], ah[i], cl);
                mm(accV[i][nb], al[i], ch);
            }
        }
    }
}
// dual-A variant: accA += A1 x B, accC += A2 x B (shared B fragments)
__device__ __forceinline__ void gemmK64_dualA(float accA[2][4][4], float accC[2][4][4],
                                              u32 A1H, u32 A1L, u32 A2H, u32 A2L,
                                              u32 BH, u32 BL, int mr, int nc, int l){
    #pragma unroll
    for (int ks = 0; ks < 4; ++ks){
        u32 ah1[2][4], al1[2][4], ah2[2][4], al2[2][4];
        ldA(A1H, mr,     ks, l, ah1[0]);
        ldA(A1H, mr+16,  ks, l, ah1[1]);
        ldA(A1L, mr,     ks, l, al1[0]);
        ldA(A1L, mr+16,  ks, l, al1[1]);
        ldA(A2H, mr,     ks, l, ah2[0]);
        ldA(A2H, mr+16,  ks, l, ah2[1]);
        ldA(A2L, mr,     ks, l, al2[0]);
        ldA(A2L, mr+16,  ks, l, al2[1]);
        #pragma unroll
        for (int nb = 0; nb < 4; ++nb){
            u32 bh[2], bl[2];
            ldB(BH, nc + nb*8, ks, l, bh);
            ldB(BL, nc + nb*8, ks, l, bl);
            #pragma unroll
            for (int i = 0; i < 2; ++i){
                mm(accA[i][nb], ah1[i], bh);
                mm(accA[i][nb], ah1[i], bl);
                mm(accA[i][nb], al1[i], bh);
                mm(accC[i][nb], ah2[i], bh);
                mm(accC[i][nb], ah2[i], bl);
                mm(accC[i][nb], al2[i], bh);
            }
        }
    }
}

// convert 64x64 fp32 chunk (row stride DIM) -> hi/lo bf16 tiles [64][72]  (128 threads)
__device__ __forceinline__ void conv_tile(u32 dh, u32 dl, const float* __restrict__ src, int t){
    #pragma unroll
    for (int i = 0; i < 8; ++i){
        int e = t + i*128;
        int row = e >> 4, c4 = e & 15;
        float4 v = *(const float4*)(src + (size_t)row*DIM + c4*4);
        __nv_bfloat16 h0=__float2bfloat16_rn(v.x), h1=__float2bfloat16_rn(v.y),
                      h2=__float2bfloat16_rn(v.z), h3=__float2bfloat16_rn(v.w);
        float l0=v.x-__bfloat162float(h0), l1=v.y-__bfloat162float(h1),
              l2=v.z-__bfloat162float(h2), l3=v.w-__bfloat162float(h3);
        u32 off = (u32)(row*144 + c4*8);
        sts64(dh + off, pack2(h0,h1), pack2(h2,h3));
        sts64(dl + off, pack2(__float2bfloat16_rn(l0),__float2bfloat16_rn(l1)),
                        pack2(__float2bfloat16_rn(l2),__float2bfloat16_rn(l3)));
    }
}
// copy 64x64 bf16 tile (row stride 'stride' elems) -> [64][72]  (128 threads)
__device__ __forceinline__ void copy_bt(u32 dst, const __nv_bfloat16* __restrict__ src, int stride, int t){
    #pragma unroll
    for (int i = 0; i < 4; ++i){
        int e = t + i*128;
        int row = e >> 3, k8 = e & 7;
        uint4 v = *(const uint4*)(src + (size_t)row*stride + k8*8);
        sts128(dst + (u32)(row*144 + k8*16), v);
    }
}
// store one fp32 value split hi/lo into bf16 tiles at (row, col)
__device__ __forceinline__ void put_split(u32 th, u32 tl, int row, int col, float x){
    u32 off = (u32)(row*144 + col*2);
    __nv_bfloat16 h = __float2bfloat16_rn(x);
    float lo = x - __bfloat162float(h);
    sts16(th + off, __bfloat16_as_ushort(h));
    sts16(tl + off, __bfloat16_as_ushort(__float2bfloat16_rn(lo)));
}

// split-store one fp32 value into global hi/lo bf16 arrays
__device__ __forceinline__ void split_st(__nv_bfloat16* H, __nv_bfloat16* L, int i, float x){
    __nv_bfloat16 h = __float2bfloat16_rn(x);
    H[i] = h;
    L[i] = __float2bfloat16_rn(x - __bfloat162float(h));
}

// ---------------- prepA: w2s (warp-per-row), invm, Gram partials ----------------
__global__ __launch_bounds__(256) void prepA_kernel(const float* __restrict__ W1,
                                                    const float* __restrict__ W2,
                                                    const float* __restrict__ mass){
    int b = blockIdx.x, t = threadIdx.x;
    if (b == 0){
        int wid = t >> 5, lane = t & 31;
        for (int row = wid; row < 64; row += 8){
            const float4* src = (const float4*)(W2 + (size_t)row*DIM);
            float s = 0.f;
            #pragma unroll
            for (int i = 0; i < 8; ++i){
                float4 v = src[lane + i*32];
                s += v.x + v.y + v.z + v.w;
            }
            #pragma unroll
            for (int o = 16; o; o >>= 1) s += __shfl_xor_sync(0xFFFFFFFFu, s, o);
            if (lane == 0) g_w2s[row] = s;
        }
        for (int i = t; i < DIM; i += 256) g_invm[i] = 1.0f / mass[i];
    } else {
        // blocks 1..32: (variant, kc) Gram partial: out[64][64] over K=64
        __shared__ float X[64*68];
        __shared__ float Y[64*68];
        int bb = b - 1;
        int variant = bb >> 4;           // 0: Gq partial, 1: Gm partial
        int kc = (bb & 15) * 64;
        for (int e = t; e < 4096; e += 256){
            int k = e >> 6, i = e & 63;
            X[k*68 + i] = W1[(size_t)(kc + k)*HID + i];
            float y;
            if (variant == 0) y = W1[(size_t)(DIM + kc + k)*HID + i];
            else              y = W1[(size_t)(kc + k)*HID + i] / mass[kc + k];
            Y[k*68 + i] = y;
        }
        __syncthreads();
        int i4 = (t & 15) * 4, j4 = (t >> 4) * 4;
        float acc[4][4] = {};
        #pragma unroll 8
        for (int k = 0; k < 64; ++k){
            float4 xv = *(const float4*)(X + k*68 + i4);
            float4 yv = *(const float4*)(Y + k*68 + j4);
            acc[0][0] = fmaf(xv.x, yv.x, acc[0][0]); acc[0][1] = fmaf(xv.x, yv.y, acc[0][1]);
            acc[0][2] = fmaf(xv.x, yv.z, acc[0][2]); acc[0][3] = fmaf(xv.x, yv.w, acc[0][3]);
            acc[1][0] = fmaf(xv.y, yv.x, acc[1][0]); acc[1][1] = fmaf(xv.y, yv.y, acc[1][1]);
            acc[1][2] = fmaf(xv.y, yv.z, acc[1][2]); acc[1][3] = fmaf(xv.y, yv.w, acc[1][3]);
            acc[2][0] = fmaf(xv.z, yv.x, acc[2][0]); acc[2][1] = fmaf(xv.z, yv.y, acc[2][1]);
            acc[2][2] = fmaf(xv.z, yv.z, acc[2][2]); acc[2][3] = fmaf(xv.z, yv.w, acc[2][3]);
            acc[3][0] = fmaf(xv.w, yv.x, acc[3][0]); acc[3][1] = fmaf(xv.w, yv.y, acc[3][1]);
            acc[3][2] = fmaf(xv.w, yv.z, acc[3][2]); acc[3][3] = fmaf(xv.w, yv.w, acc[3][3]);
        }
        float* dst = g_part + bb*4096;
        #pragma unroll
        for (int ii = 0; ii < 4; ++ii)
            #pragma unroll
            for (int jj = 0; jj < 4; ++jj)
                dst[(i4+ii)*64 + j4+jj] = acc[ii][jj];
    }
}

// ---------------- prepB: fixed-order reduction of Gram partials (32 blocks) ----------------
__global__ __launch_bounds__(256) void prepB_kernel(){
    int b = blockIdx.x, t = threadIdx.x;
    int variant = b >> 4;
    int e = (b & 15)*256 + t;
    float s = 0.f;
    #pragma unroll
    for (int c = 0; c < 16; ++c)
        s += g_part[(variant*16 + c)*4096 + e];
    (variant ? g_Gm : g_Gq)[e] = s;
}

// ---------------- prep2: coalesced tiled-transpose bf16 hi/lo splits ----------------
__global__ __launch_bounds__(256) void prep2_kernel(const float* __restrict__ W1,
                                                    const float* __restrict__ W2,
                                                    const float* __restrict__ dtp){
    __shared__ float T[64][65];
    int b = blockIdx.x, t = threadIdx.x;
    float dt = dt_of(dtp), hdt = 0.5f*dt, dthdt = dt*hdt;
    if (b < 16){
        int k0 = b*64;
        // W1q tile: coalesced read; direct-layout W1qB while loading
        for (int e = t; e < 4096; e += 256){
            int r = e >> 6, c = e & 63;
            float v = W1[(size_t)(k0 + r)*HID + c];
            T[r][c] = v;
            split_st(g_W1qB_h, g_W1qB_l, (k0 + r)*HID + c, v);
        }
        __syncthreads();
        // transposed outputs W1qT / W1qmT (coalesced writes over k)
        for (int e = t; e < 4096; e += 256){
            int j = e >> 6, k = e & 63;
            float v = T[k][j];
            int o = j*DIM + k0 + k;
            split_st(g_W1qT_h,  g_W1qT_l,  o, v);
            split_st(g_W1qmT_h, g_W1qmT_l, o, v * g_invm[k0 + k]);
        }
        __syncthreads();
        // W1p tile
        for (int e = t; e < 4096; e += 256){
            int r = e >> 6, c = e & 63;
            T[r][c] = W1[(size_t)(DIM + k0 + r)*HID + c];
        }
        __syncthreads();
        for (int e = t; e < 4096; e += 256){
            int j = e >> 6, k = e & 63;
            split_st(g_W1pT_h, g_W1pT_l, j*DIM + k0 + k, T[k][j]);
        }
    } else if (b < 32){
        int d0 = (b - 16)*64;
        // W2 tile: read coalesced along d, write transposed coalesced along j
        for (int e = t; e < 4096; e += 256){
            int j = e >> 6, c = e & 63;
            T[j][c] = W2[(size_t)j*DIM + d0 + c];
        }
        __syncthreads();
        for (int e = t; e < 4096; e += 256){
            int d = e >> 6, j = e & 63;
            split_st(g_W2TB_h, g_W2TB_l, (d0 + d)*HID + j, T[j][d]);
        }
    } else {
        // Gram-derived tiles (transposed, scaled)
        for (int e = t; e < 4096; e += 256){
            int j2 = e >> 6, j1 = e & 63;
            float gq = g_Gq[j1*HID + j2];
            float gm = g_Gm[j1*HID + j2];
            split_st(g_G1T_h, g_G1T_l, e, hdt*gq + dthdt*gm);
            split_st(g_GqT_h, g_GqT_l, e, hdt*gq);
        }
    }
}

// ---------------- smem layout (bytes) — 64-row CTA, X aliased with S1 (R12) ----------------
#define XH_   0u            // phase 1 staging (dead after phase 1)
#define XL_   9216u
#define S1H_  0u            // s1 tiles written phase 2 (alias X)
#define S1L_  9216u
#define B0H_  18432u
#define B0L_  27648u
#define B1H_  36864u
#define B1L_  46080u
#define CTH_  55296u
#define CTL_  64512u
#define ETH_  73728u
#define ETL_  82944u
#define CB1_  92160u
#define CWS_  92416u
#define SMEM_TOTAL 92672

// ---------------- mega kernel: 64 rows per CTA, 128 threads, 2 CTAs/SM (R12 verbatim) ----------------
__global__ __launch_bounds__(128, 2) void mega(const float* __restrict__ q,
                                               const float* __restrict__ p,
                                               const float* __restrict__ b1,
                                               const float* __restrict__ dtp,
                                               float* __restrict__ out_q,
                                               float* __restrict__ out_p,
                                               float* __restrict__ out_e){
    extern __shared__ char smem[];
    u32 SB = s2u(smem);
    int t = threadIdx.x, w = t >> 5, l = t & 31;
    int mr = (w & 1) * 32;         // warp row base within 64
    int nc = (w >> 1) * 32;        // warp col base within 64
    int r0 = blockIdx.x * 64;
    float dt = dt_of(dtp), hdt = 0.5f*dt;

    if (t < 64){
        sts32f(SB + CB1_ + t*4, __ldg(b1 + t));
        sts32f(SB + CWS_ + t*4, g_w2s[t]);
    }

    // ================= phase 1: Z and V accumulation over K =================
    float accZ[2][4][4], accV[2][4][4];
    #pragma unroll
    for (int i = 0; i < 2; ++i)
        #pragma unroll
        for (int nb = 0; nb < 4; ++nb)
            #pragma unroll
            for (int c = 0; c < 4; ++c){ accZ[i][nb][c] = 0.f; accV[i][nb][c] = 0.f; }

    for (int ch = 0; ch < 32; ++ch){
        int is_p = (ch >= 16);
        int kk = (ch & 15) * 64;
        __syncthreads();
        conv_tile(SB+XH_, SB+XL_, (is_p ? p : q) + (size_t)r0*DIM + kk, t);
        if (!is_p){
            copy_bt(SB+B0H_, g_W1qT_h + kk, DIM, t);
            copy_bt(SB+B0L_, g_W1qT_l + kk, DIM, t);
        } else {
            copy_bt(SB+B0H_, g_W1pT_h + kk, DIM, t);
            copy_bt(SB+B0L_, g_W1pT_l + kk, DIM, t);
            copy_bt(SB+B1H_, g_W1qmT_h + kk, DIM, t);
            copy_bt(SB+B1L_, g_W1qmT_l + kk, DIM, t);
        }
        __syncthreads();
        if (!is_p){
            gemmK64(accZ, SB+XH_, SB+XL_, SB+B0H_, SB+B0L_, mr, nc, l);
        } else {
            gemmK64_dualB(accZ, accV, SB+XH_, SB+XL_,
                          SB+B0H_, SB+B0L_, SB+B1H_, SB+B1L_, mr, nc, l);
        }
    }
    __syncthreads();   // phase-1 gemms done reading X region before S1 overwrites it

    // ================= phase 2: z1, s1 =================
    float z1r[2][4][4], z2r[2][4][4];
    #pragma unroll
    for (int i = 0; i < 2; ++i)
        #pragma unroll
        for (int nb = 0; nb < 4; ++nb){
            int colb = nc + nb*8 + 2*(l & 3);
            #pragma unroll
            for (int c = 0; c < 4; ++c){
                int col = colb + (c & 1);
                int row = mr + i*16 + (l >> 2) + 8*(c >> 1);
                float z1 = accZ[i][nb][c] + ldsf(SB + CB1_ + col*4);
                float ws = ldsf(SB + CWS_ + col*4);
                z1r[i][nb][c] = z1;
                z2r[i][nb][c] = fmaf(dt, accV[i][nb][c], z1);   // z1 + dt*v (corr pending)
                put_split(SB+S1H_, SB+S1L_, row, col, dgelu_f(z1)*ws);
            }
        }
    // Gram tiles: B0 = G1T (hdt*Gq + dt*hdt*Gm), B1 = GqT (hdt*Gq)
    copy_bt(SB+B0H_, g_G1T_h, 64, t);
    copy_bt(SB+B0L_, g_G1T_l, 64, t);
    copy_bt(SB+B1H_, g_GqT_h, 64, t);
    copy_bt(SB+B1L_, g_GqT_l, 64, t);
    __syncthreads();

    // ================= phase 3: corr = s1@G1 ; z2, s2 =================
    {
        float cr[2][4][4] = {};
        gemmK64(cr, SB+S1H_, SB+S1L_, SB+B0H_, SB+B0L_, mr, nc, l);
        #pragma unroll
        for (int i = 0; i < 2; ++i)
            #pragma unroll
            for (int nb = 0; nb < 4; ++nb){
                int colb = nc + nb*8 + 2*(l & 3);
                #pragma unroll
                for (int c = 0; c < 4; ++c){
                    int col = colb + (c & 1);
                    int row = mr + i*16 + (l >> 2) + 8*(c >> 1);
                    float z2 = z2r[i][nb][c] - cr[i][nb][c];
                    z2r[i][nb][c] = z2;
                    float ws = ldsf(SB + CWS_ + col*4);
                    put_split(SB+CTH_, SB+CTL_, row, col, dgelu_f(z2)*ws);   // s2
                }
            }
    }
    __syncthreads();

    // ================= phase 4: c3 = s2@(hdt*Gq) ; E, C =================
    {
        float c3[2][4][4] = {};
        gemmK64(c3, SB+CTH_, SB+CTL_, SB+B1H_, SB+B1L_, mr, nc, l);
        __syncthreads();   // everyone done reading CT before overwrite
        #pragma unroll
        for (int i = 0; i < 2; ++i)
            #pragma unroll
            for (int nb = 0; nb < 4; ++nb){
                int colb = nc + nb*8 + 2*(l & 3);
                #pragma unroll
                for (int c = 0; c < 4; ++c){
                    int col = colb + (c & 1);
                    int row = mr + i*16 + (l >> 2) + 8*(c >> 1);
                    float z1 = z1r[i][nb][c];
                    float z2 = z2r[i][nb][c];
                    float z3 = z2 - c3[i][nb][c];
                    float ws = ldsf(SB + CWS_ + col*4);
                    put_split(SB+ETH_, SB+ETL_, row, col, gelu_f(z1) - gelu_f(z3));       // E
                    put_split(SB+CTH_, SB+CTL_, row, col, (dgelu_f(z1) + dgelu_f(z2))*ws); // C
                }
            }
    }

    // ================= phase 5: d-loop =================
    for (int dc = 0; dc < 16; ++dc){
        int d0 = dc * 64;
        __syncthreads();
        copy_bt(SB+B0H_, g_W1qB_h + (size_t)d0*HID, HID, t);
        copy_bt(SB+B0L_, g_W1qB_l + (size_t)d0*HID, HID, t);
        copy_bt(SB+B1H_, g_W2TB_h + (size_t)d0*HID, HID, t);
        copy_bt(SB+B1L_, g_W2TB_l + (size_t)d0*HID, HID, t);
        __syncthreads();

        float aq[2][4][4] = {}, cc[2][4][4] = {};
        gemmK64_dualA(aq, cc, SB+S1H_, SB+S1L_, SB+CTH_, SB+CTL_,
                      SB+B0H_, SB+B0L_, mr, nc, l);
        #pragma unroll
        for (int i = 0; i < 2; ++i)
            #pragma unroll
            for (int nb = 0; nb < 4; ++nb){
                int col = nc + nb*8 + 2*(l & 3);
                #pragma unroll
                for (int h = 0; h < 2; ++h){
                    int row = mr + i*16 + (l >> 2) + 8*h;
                    size_t off = (size_t)(r0 + row)*DIM + d0 + col;
                    float2 qv = *(const float2*)(q + off);
                    float2 pv = *(const float2*)(p + off);
                    float2 iv = *(const float2*)(g_invm + d0 + col);
                    float a0 = aq[i][nb][2*h], a1 = aq[i][nb][2*h+1];
                    float c0 = cc[i][nb][2*h], c1 = cc[i][nb][2*h+1];
                    float2 qn, pn;
                    qn.x = qv.x + dt*iv.x*(pv.x - hdt*a0);
                    qn.y = qv.y + dt*iv.y*(pv.y - hdt*a1);
                    pn.x = pv.x - hdt*c0;
                    pn.y = pv.y - hdt*c1;
                    *(float2*)(out_q + off) = qn;
                    *(float2*)(out_p + off) = pn;
                }
            }

        float ec[2][4][4] = {};
        gemmK64(ec, SB+ETH_, SB+ETL_, SB+B1H_, SB+B1L_, mr, nc, l);
        #pragma unroll
        for (int i = 0; i < 2; ++i)
            #pragma unroll
            for (int nb = 0; nb < 4; ++nb){
                int col = nc + nb*8 + 2*(l & 3);
                #pragma unroll
                for (int h = 0; h < 2; ++h){
                    int row = mr + i*16 + (l >> 2) + 8*h;
                    size_t off = (size_t)(r0 + row)*DIM + d0 + col;
                    float2 ev;
                    ev.x = fabsf(ec[i][nb][2*h]);
                    ev.y = fabsf(ec[i][nb][2*h+1]);
                    *(float2*)(out_e + off) = ev;
                }
            }
    }
}

// ---------------- launch ----------------
extern "C" void kernel_launch(void* const* d_in, const int* in_sizes, int n_in,
                              void* d_out, int out_size){
    const float* q    = (const float*)d_in[0];
    const float* p    = (const float*)d_in[1];
    const float* W1   = (const float*)d_in[2];
    const float* b1   = (const float*)d_in[3];
    const float* W2   = (const float*)d_in[4];
    const float* mass = (const float*)d_in[6];
    const float* dtp  = (const float*)d_in[7];
    float* out_q = (float*)d_out;
    float* out_p = out_q + (size_t)BB*DIM;
    float* out_e = out_p + (size_t)BB*DIM;

    cudaFuncSetAttribute(mega, cudaFuncAttributeMaxDynamicSharedMemorySize, SMEM_TOTAL);

    prepA_kernel<<<33, 256>>>(W1, W2, mass);
    prepB_kernel<<<32, 256>>>();
    prep2_kernel<<<33, 256>>>(W1, W2, dtp);
    mega<<<BB/64, 128, SMEM_TOTAL>>>(q, p, b1, dtp, out_q, out_p, out_e);
}